// round 11
// baseline (speedup 1.0000x reference)
#include <cuda_runtime.h>
#include <cuda_bf16.h>
#include <math.h>
#include <stdint.h>

// ---------------------------------------------------------------------------
// Scratch (allocation-free rule: device globals)
// ---------------------------------------------------------------------------
__device__ __nv_bfloat16 g_xh[4096 * 1024],  g_xl[4096 * 1024];
__device__ __nv_bfloat16 g_wqh[3072 * 1024], g_wql[3072 * 1024];
__device__ __nv_bfloat16 g_woh[1024 * 1024], g_wol[1024 * 1024];
__device__ __nv_bfloat16 g_qh[4096 * 3072],  g_ql[4096 * 3072];   // qkv hi/lo
__device__ __nv_bfloat16 g_ah[4096 * 1024],  g_al[4096 * 1024];   // attn hi/lo

// ---------------------------------------------------------------------------
// Helpers
// ---------------------------------------------------------------------------
__device__ __forceinline__ uint32_t smem_u32(const void* p) {
    uint32_t a;
    asm("{ .reg .u64 t; cvta.to.shared.u64 t, %1; cvt.u32.u64 %0, t; }" : "=r"(a) : "l"(p));
    return a;
}
__device__ __forceinline__ float ex2(float x) {
    float r; asm("ex2.approx.f32 %0, %1;" : "=f"(r) : "f"(x)); return r;
}
// split two floats into packed bf16 hi-pair + lo-pair (x -> low half, y -> high)
__device__ __forceinline__ void split2(float x, float y, uint32_t& hi, uint32_t& lo) {
    uint32_t h;
    asm("cvt.rn.bf16x2.f32 %0, %1, %2;" : "=r"(h) : "f"(y), "f"(x));
    float hx = __uint_as_float(h << 16);
    float hy = __uint_as_float(h & 0xffff0000u);
    float lx = x - hx, ly = y - hy;
    uint32_t l;
    asm("cvt.rn.bf16x2.f32 %0, %1, %2;" : "=r"(l) : "f"(ly), "f"(lx));
    hi = h; lo = l;
}
__device__ __forceinline__ void split4(float4 v, uint2& hi, uint2& lo) {
    split2(v.x, v.y, hi.x, lo.x);
    split2(v.z, v.w, hi.y, lo.y);
}
__device__ __forceinline__ void mma_bf16(float c[4], const uint32_t a[4],
                                         uint32_t b0, uint32_t b1) {
    asm volatile(
        "mma.sync.aligned.m16n8k16.row.col.f32.bf16.bf16.f32 "
        "{%0,%1,%2,%3}, {%4,%5,%6,%7}, {%8,%9}, {%0,%1,%2,%3};"
        : "+f"(c[0]), "+f"(c[1]), "+f"(c[2]), "+f"(c[3])
        : "r"(a[0]), "r"(a[1]), "r"(a[2]), "r"(a[3]), "r"(b0), "r"(b1));
}
__device__ __forceinline__ void ldm_x4(uint32_t r[4], uint32_t addr) {
    asm volatile("ldmatrix.sync.aligned.m8n8.x4.shared.b16 {%0,%1,%2,%3}, [%4];"
                 : "=r"(r[0]), "=r"(r[1]), "=r"(r[2]), "=r"(r[3]) : "r"(addr));
}
__device__ __forceinline__ void ldm_x4_trans(uint32_t r[4], uint32_t addr) {
    asm volatile("ldmatrix.sync.aligned.m8n8.x4.trans.shared.b16 {%0,%1,%2,%3}, [%4];"
                 : "=r"(r[0]), "=r"(r[1]), "=r"(r[2]), "=r"(r[3]) : "r"(addr));
}
__device__ __forceinline__ void cp16(uint32_t saddr, const void* g) {
    asm volatile("cp.async.cg.shared.global [%0], [%1], 16;" :: "r"(saddr), "l"(g));
}
#define CP_COMMIT() asm volatile("cp.async.commit_group;" ::: "memory")
#define CP_WAIT1()  asm volatile("cp.async.wait_group 1;" ::: "memory")

// ---------------------------------------------------------------------------
// split kernel: fp32 -> (hi, lo) bf16 arrays
// ---------------------------------------------------------------------------
__global__ void split_kernel(const float* __restrict__ in,
                             __nv_bfloat16* __restrict__ hi,
                             __nv_bfloat16* __restrict__ lo, int n4) {
    int i = blockIdx.x * blockDim.x + threadIdx.x;
    if (i < n4) {
        float4 v = ((const float4*)in)[i];
        uint2 h, l;
        split4(v, h, l);
        ((uint2*)hi)[i] = h;
        ((uint2*)lo)[i] = l;
    }
}

// ---------------------------------------------------------------------------
// bf16x3 split GEMM, raw mma.sync + ldmatrix + cp.async, 2-stage, 2 CTA/SM.
//   C[M,N] = A[M,K] @ B[N,K]^T;  epilogue: fp32 C  OR  bf16 hi/lo split pair.
// ---------------------------------------------------------------------------
#define GP     40
#define ARR_B  (128 * GP * 2)
#define STG_B  (4 * ARR_B)
#define NSTG   2
#define GEMM_SMEM (NSTG * STG_B)     // 81920 B -> 2 CTAs/SM

template <bool SPLITC>
__global__ __launch_bounds__(256, 2) void gemm_mma(const __nv_bfloat16* __restrict__ Ahg,
                                                   const __nv_bfloat16* __restrict__ Alg,
                                                   const __nv_bfloat16* __restrict__ Bhg,
                                                   const __nv_bfloat16* __restrict__ Blg,
                                                   float* __restrict__ C,
                                                   __nv_bfloat16* __restrict__ Ch,
                                                   __nv_bfloat16* __restrict__ Cl,
                                                   int K, int N) {
    extern __shared__ __align__(16) char gsm[];
    const uint32_t sbase = smem_u32(gsm);

    const int tid = threadIdx.x;
    const int wid = tid >> 5;
    const int lane = tid & 31;
    const int wr = wid >> 2;
    const int wc = wid & 3;
    const int gr = lane >> 2, qq = lane & 3;
    const int row0 = blockIdx.y * 128;
    const int col0 = blockIdx.x * 128;
    const int NCH = K >> 5;

    auto load_chunk = [&](int kc, int stg) {
        const uint32_t st = sbase + stg * STG_B;
#pragma unroll
        for (int t = 0; t < 8; t++) {
            int idx = tid + t * 256;
            int arr = idx >> 9;
            int i = idx & 511;
            int row = i >> 2;
            int ch = i & 3;
            uint32_t sa = st + arr * ARR_B + (row * GP + ch * 8) * 2;
            const __nv_bfloat16* gp;
            int kcol = kc * 32 + ch * 8;
            if (arr == 0)      gp = &Ahg[(size_t)(row0 + row) * K + kcol];
            else if (arr == 1) gp = &Alg[(size_t)(row0 + row) * K + kcol];
            else if (arr == 2) gp = &Bhg[(size_t)(col0 + row) * K + kcol];
            else               gp = &Blg[(size_t)(col0 + row) * K + kcol];
            cp16(sa, gp);
        }
    };

    float acc[4][4][4] = {};

    load_chunk(0, 0);
    CP_COMMIT();
    load_chunk(1, 1);
    CP_COMMIT();

    const uint32_t lrow = lane & 15;
    const uint32_t lcol8 = (lane >> 4) << 3;

    for (int c = 0; c < NCH; c++) {
        CP_WAIT1();
        __syncthreads();

        const uint32_t st = sbase + (c & 1) * STG_B;
        const uint32_t ah = st, al = st + ARR_B, bh = st + 2 * ARR_B, bl = st + 3 * ARR_B;
#pragma unroll
        for (int ks = 0; ks < 2; ks++) {
            const uint32_t koff = (ks * 16 + lcol8) * 2;
            // --- term 1: Ah * Bh ---
            uint32_t fa[4][4], fb[4][2];
#pragma unroll
            for (int i = 0; i < 4; i++)
                ldm_x4(fa[i], ah + ((wr * 64 + i * 16 + lrow) * GP) * 2 + koff);
#pragma unroll
            for (int g = 0; g < 2; g++) {
                uint32_t r[4];
                ldm_x4(r, bh + ((wc * 32 + g * 16 + lrow) * GP) * 2 + koff);
                fb[2 * g][0] = r[0]; fb[2 * g][1] = r[2];
                fb[2 * g + 1][0] = r[1]; fb[2 * g + 1][1] = r[3];
            }
#pragma unroll
            for (int i = 0; i < 4; i++)
#pragma unroll
                for (int j = 0; j < 4; j++)
                    mma_bf16(acc[i][j], fa[i], fb[j][0], fb[j][1]);
            // --- term 2: Ah * Bl ---
            uint32_t fbl[4][2];
#pragma unroll
            for (int g = 0; g < 2; g++) {
                uint32_t r[4];
                ldm_x4(r, bl + ((wc * 32 + g * 16 + lrow) * GP) * 2 + koff);
                fbl[2 * g][0] = r[0]; fbl[2 * g][1] = r[2];
                fbl[2 * g + 1][0] = r[1]; fbl[2 * g + 1][1] = r[3];
            }
#pragma unroll
            for (int i = 0; i < 4; i++)
#pragma unroll
                for (int j = 0; j < 4; j++)
                    mma_bf16(acc[i][j], fa[i], fbl[j][0], fbl[j][1]);
            // --- term 3: Al * Bh ---
#pragma unroll
            for (int i = 0; i < 4; i++)
                ldm_x4(fa[i], al + ((wr * 64 + i * 16 + lrow) * GP) * 2 + koff);
#pragma unroll
            for (int i = 0; i < 4; i++)
#pragma unroll
                for (int j = 0; j < 4; j++)
                    mma_bf16(acc[i][j], fa[i], fb[j][0], fb[j][1]);
        }
        __syncthreads();
        int nc = c + NSTG;
        if (nc < NCH) load_chunk(nc, c & 1);
        CP_COMMIT();
    }

    // epilogue
#pragma unroll
    for (int i = 0; i < 4; i++) {
        int r0g = row0 + wr * 64 + i * 16 + gr;
#pragma unroll
        for (int j = 0; j < 4; j++) {
            int cg = col0 + wc * 32 + j * 8 + 2 * qq;
            if (SPLITC) {
                uint32_t hi, lo;
                split2(acc[i][j][0], acc[i][j][1], hi, lo);
                *(uint32_t*)&Ch[(size_t)r0g * N + cg] = hi;
                *(uint32_t*)&Cl[(size_t)r0g * N + cg] = lo;
                split2(acc[i][j][2], acc[i][j][3], hi, lo);
                *(uint32_t*)&Ch[(size_t)(r0g + 8) * N + cg] = hi;
                *(uint32_t*)&Cl[(size_t)(r0g + 8) * N + cg] = lo;
            } else {
                *(float2*)&C[(size_t)r0g * N + cg] = make_float2(acc[i][j][0], acc[i][j][1]);
                *(float2*)&C[(size_t)(r0g + 8) * N + cg] = make_float2(acc[i][j][2], acc[i][j][3]);
            }
        }
    }
}

// ---------------------------------------------------------------------------
// Flash attention on tensor cores, bf16 hi/lo in/out, cp.async double-buffer.
// CTA: 128 q-rows x one (b,h); 8 warps x 16 q-rows; 32 key-tiles of 64.
// K frags via ldmatrix.x4, V frags via ldmatrix.x4.trans.
// ---------------------------------------------------------------------------
#define FP     72                       // bf16 row pitch (144 B)
#define FQ_B   (128 * FP * 2)           // Q array bytes (18432)
#define KV_B   (64 * FP * 2)            // KV array bytes (9216)
#define KVS_B  (4 * KV_B)               // KV stage bytes (36864)
#define FLASH_SMEM (2 * FQ_B + 2 * KVS_B)   // 110592

__global__ __launch_bounds__(256, 2) void flash_attn(const __nv_bfloat16* __restrict__ qh,
                                                     const __nv_bfloat16* __restrict__ ql,
                                                     __nv_bfloat16* __restrict__ oh,
                                                     __nv_bfloat16* __restrict__ ol) {
    extern __shared__ __align__(16) char fsmc[];
    const uint32_t sb = smem_u32(fsmc);
    __nv_bfloat16* Qh = (__nv_bfloat16*)fsmc;

    const int tid = threadIdx.x;
    const int wid = tid >> 5;
    const int lane = tid & 31;
    const int gr = lane >> 2;
    const int qq = lane & 3;

    const int qt = blockIdx.x;
    const int b  = blockIdx.y >> 4;
    const int h  = blockIdx.y & 15;

    const size_t tok0 = (size_t)b * 2048;
    const int qoff = h * 64, koff = 1024 + h * 64, voff = 2048 + h * 64;
    const float QS = 0.125f * 1.4426950408889634f;   // 1/sqrt(64) * log2(e)

    // ---- async load Q (2 arrays x 128 rows x 8 chunks) ----
#pragma unroll
    for (int i = 0; i < 8; i++) {
        int idx = tid + i * 256;
        int arr = idx >> 10;
        int rem = idx & 1023;
        int row = rem >> 3, ch = rem & 7;
        const __nv_bfloat16* src = (arr ? ql : qh) +
            (tok0 + qt * 128 + row) * 3072 + qoff + ch * 8;
        cp16(sb + arr * FQ_B + row * 144 + ch * 16, src);
    }
    // KV tile loader: 4 arrays x 64 rows x 8 chunks = 2048 -> 8/thread
    auto load_kv = [&](int kt, int s) {
        const uint32_t st = sb + 2 * FQ_B + s * KVS_B;
#pragma unroll
        for (int i = 0; i < 8; i++) {
            int idx = tid + i * 256;
            int arr = idx >> 9;
            int rem = idx & 511;
            int row = rem >> 3, ch = rem & 7;
            int gcol = (arr < 2 ? koff : voff) + ch * 8;
            const __nv_bfloat16* src = ((arr & 1) ? ql : qh) +
                (tok0 + kt * 64 + row) * 3072 + gcol;
            cp16(st + arr * KV_B + row * 144 + ch * 16, src);
        }
    };

    load_kv(0, 0);
    CP_COMMIT();                  // g0: Q + KV0
    load_kv(1, 1);
    CP_COMMIT();                  // g1: KV1
    CP_WAIT1();                   // g0 done
    __syncthreads();

    // ---- Q-hi A-fragments resident in regs; Q-lo reloaded per tile ----
    uint32_t qa_h[4][4];
    const int qrow = wid * 16;
    const uint32_t ql_u = sb + FQ_B;
    const uint32_t lrow16 = lane & 15;
    const uint32_t lcol8 = (lane >> 4) << 3;
    const uint32_t qfrag_off = (qrow + lrow16) * 144 + lcol8 * 2;
#pragma unroll
    for (int kap = 0; kap < 4; kap++) {
        int cb = kap * 16 + 2 * qq;
        qa_h[kap][0] = *(const uint32_t*)&Qh[(qrow + gr) * FP + cb];
        qa_h[kap][1] = *(const uint32_t*)&Qh[(qrow + gr + 8) * FP + cb];
        qa_h[kap][2] = *(const uint32_t*)&Qh[(qrow + gr) * FP + cb + 8];
        qa_h[kap][3] = *(const uint32_t*)&Qh[(qrow + gr + 8) * FP + cb + 8];
    }

    float m0 = -1e30f, m1 = -1e30f, l0 = 0.0f, l1 = 0.0f;
    float o[8][4] = {};

    for (int kt = 0; kt < 32; kt++) {
        const uint32_t st = sb + 2 * FQ_B + (kt & 1) * KVS_B;
        const uint32_t kh_u = st;
        const uint32_t kl_u = st + KV_B;
        const uint32_t vh_u = st + 2 * KV_B;
        const uint32_t vl_u = st + 3 * KV_B;

        // ---- S = Q @ K^T  (K frags via ldmatrix.x4, same pattern as GEMM B) ----
        float S[8][4];
#pragma unroll
        for (int j = 0; j < 8; j++) { S[j][0] = S[j][1] = S[j][2] = S[j][3] = 0.0f; }
#pragma unroll
        for (int kap = 0; kap < 4; kap++) {
            uint32_t qa_l[4];
            ldm_x4(qa_l, ql_u + qfrag_off + kap * 32);
            const uint32_t koff2 = (kap * 16 + lcol8) * 2;
#pragma unroll
            for (int jp = 0; jp < 4; jp++) {
                uint32_t rh[4], rl[4];
                const uint32_t rowa = (jp * 16 + lrow16) * 144 + koff2;
                ldm_x4(rh, kh_u + rowa);
                ldm_x4(rl, kl_u + rowa);
                mma_bf16(S[2 * jp],     qa_h[kap], rh[0], rh[2]);
                mma_bf16(S[2 * jp + 1], qa_h[kap], rh[1], rh[3]);
                mma_bf16(S[2 * jp],     qa_h[kap], rl[0], rl[2]);
                mma_bf16(S[2 * jp + 1], qa_h[kap], rl[1], rl[3]);
                mma_bf16(S[2 * jp],     qa_l, rh[0], rh[2]);
                mma_bf16(S[2 * jp + 1], qa_l, rh[1], rh[3]);
            }
        }
#pragma unroll
        for (int j = 0; j < 8; j++) {
            S[j][0] *= QS; S[j][1] *= QS; S[j][2] *= QS; S[j][3] *= QS;
        }

        // ---- online softmax ----
        float t0 = -1e30f, t1 = -1e30f;
#pragma unroll
        for (int j = 0; j < 8; j++) {
            t0 = fmaxf(t0, fmaxf(S[j][0], S[j][1]));
            t1 = fmaxf(t1, fmaxf(S[j][2], S[j][3]));
        }
        t0 = fmaxf(t0, __shfl_xor_sync(0xffffffffu, t0, 1));
        t0 = fmaxf(t0, __shfl_xor_sync(0xffffffffu, t0, 2));
        t1 = fmaxf(t1, __shfl_xor_sync(0xffffffffu, t1, 1));
        t1 = fmaxf(t1, __shfl_xor_sync(0xffffffffu, t1, 2));
        float mn0 = fmaxf(m0, t0), mn1 = fmaxf(m1, t1);
        float al0 = ex2(m0 - mn0), al1 = ex2(m1 - mn1);
        m0 = mn0; m1 = mn1;

        float rs0 = 0.0f, rs1 = 0.0f;
#pragma unroll
        for (int j = 0; j < 8; j++) {
            S[j][0] = ex2(S[j][0] - m0);
            S[j][1] = ex2(S[j][1] - m0);
            S[j][2] = ex2(S[j][2] - m1);
            S[j][3] = ex2(S[j][3] - m1);
            rs0 += S[j][0] + S[j][1];
            rs1 += S[j][2] + S[j][3];
        }
        rs0 += __shfl_xor_sync(0xffffffffu, rs0, 1);
        rs0 += __shfl_xor_sync(0xffffffffu, rs0, 2);
        rs1 += __shfl_xor_sync(0xffffffffu, rs1, 1);
        rs1 += __shfl_xor_sync(0xffffffffu, rs1, 2);
        l0 = l0 * al0 + rs0;
        l1 = l1 * al1 + rs1;
#pragma unroll
        for (int jn = 0; jn < 8; jn++) {
            o[jn][0] *= al0; o[jn][1] *= al0;
            o[jn][2] *= al1; o[jn][3] *= al1;
        }

        // ---- split P (all 4 k16 groups) into bf16 hi/lo A-fragments ----
        uint32_t ph[4][4], pl[4][4];
#pragma unroll
        for (int kap = 0; kap < 4; kap++) {
            const float* s0 = S[2 * kap];
            const float* s1 = S[2 * kap + 1];
            split2(s0[0], s0[1], ph[kap][0], pl[kap][0]);
            split2(s0[2], s0[3], ph[kap][1], pl[kap][1]);
            split2(s1[0], s1[1], ph[kap][2], pl[kap][2]);
            split2(s1[2], s1[3], ph[kap][3], pl[kap][3]);
        }

        // ---- O += P @ V  (V frags via ldmatrix.x4.trans: 32 rows/instr) ----
#pragma unroll
        for (int jn = 0; jn < 8; jn++) {
#pragma unroll
            for (int kp2 = 0; kp2 < 2; kp2++) {
                uint32_t vh4[4], vl4[4];
                const uint32_t rowa = (kp2 * 32 + lane) * 144 + jn * 16;
                ldm_x4_trans(vh4, vh_u + rowa);
                ldm_x4_trans(vl4, vl_u + rowa);
                mma_bf16(o[jn], ph[2 * kp2],     vh4[0], vh4[1]);
                mma_bf16(o[jn], ph[2 * kp2],     vl4[0], vl4[1]);
                mma_bf16(o[jn], pl[2 * kp2],     vh4[0], vh4[1]);
                mma_bf16(o[jn], ph[2 * kp2 + 1], vh4[2], vh4[3]);
                mma_bf16(o[jn], ph[2 * kp2 + 1], vl4[2], vl4[3]);
                mma_bf16(o[jn], pl[2 * kp2 + 1], vh4[2], vh4[3]);
            }
        }

        // ---- prefetch KV(kt+2) into the stage just consumed ----
        __syncthreads();
        if (kt + 2 < 32) load_kv(kt + 2, kt & 1);
        CP_COMMIT();
        if (kt + 1 < 32) {
            CP_WAIT1();
            __syncthreads();
        }
    }

    // ---- epilogue: normalize, split, store bf16 hi/lo (b, s, h*64+d) ----
    float inv0 = 1.0f / l0, inv1 = 1.0f / l1;
    const size_t row0 = (tok0 + qt * 128 + wid * 16 + gr) * 1024 + h * 64;
    const size_t row1 = row0 + 8 * 1024;
#pragma unroll
    for (int jn = 0; jn < 8; jn++) {
        int cc = jn * 8 + 2 * qq;
        uint32_t hi, lo;
        split2(o[jn][0] * inv0, o[jn][1] * inv0, hi, lo);
        *(uint32_t*)&oh[row0 + cc] = hi;
        *(uint32_t*)&ol[row0 + cc] = lo;
        split2(o[jn][2] * inv1, o[jn][3] * inv1, hi, lo);
        *(uint32_t*)&oh[row1 + cc] = hi;
        *(uint32_t*)&ol[row1 + cc] = lo;
    }
}

// ---------------------------------------------------------------------------
// Launch: split inputs -> QKV GEMM (split out) -> flash (split out) -> out GEMM
// ---------------------------------------------------------------------------
extern "C" void kernel_launch(void* const* d_in, const int* in_sizes, int n_in,
                              void* d_out, int out_size) {
    const float* x     = (const float*)d_in[0];  // [2,2048,1024]
    const float* w_qkv = (const float*)d_in[1];  // [3072,1024]
    const float* w_out = (const float*)d_in[2];  // [1024,1024]
    float* out = (float*)d_out;                  // [2,2048,1024]

    __nv_bfloat16 *xh, *xl, *wqh, *wql, *woh, *wol, *qh, *ql, *ah, *al;
    cudaGetSymbolAddress((void**)&xh, g_xh);   cudaGetSymbolAddress((void**)&xl, g_xl);
    cudaGetSymbolAddress((void**)&wqh, g_wqh); cudaGetSymbolAddress((void**)&wql, g_wql);
    cudaGetSymbolAddress((void**)&woh, g_woh); cudaGetSymbolAddress((void**)&wol, g_wol);
    cudaGetSymbolAddress((void**)&qh, g_qh);   cudaGetSymbolAddress((void**)&ql, g_ql);
    cudaGetSymbolAddress((void**)&ah, g_ah);   cudaGetSymbolAddress((void**)&al, g_al);

    cudaFuncSetAttribute(flash_attn, cudaFuncAttributeMaxDynamicSharedMemorySize, FLASH_SMEM);
    cudaFuncSetAttribute(gemm_mma<true>, cudaFuncAttributeMaxDynamicSharedMemorySize, GEMM_SMEM);
    cudaFuncSetAttribute(gemm_mma<false>, cudaFuncAttributeMaxDynamicSharedMemorySize, GEMM_SMEM);

    dim3 blk(256);
    split_kernel<<<(4096 * 1024 / 4 + 255) / 256, blk>>>(x, xh, xl, 4096 * 1024 / 4);
    split_kernel<<<(3072 * 1024 / 4 + 255) / 256, blk>>>(w_qkv, wqh, wql, 3072 * 1024 / 4);
    split_kernel<<<(1024 * 1024 / 4 + 255) / 256, blk>>>(w_out, woh, wol, 1024 * 1024 / 4);
    // QKV: [4096,3072] = x @ w_qkv^T  -> bf16 hi/lo
    gemm_mma<true><<<dim3(3072 / 128, 4096 / 128), blk, GEMM_SMEM>>>(
        xh, xl, wqh, wql, nullptr, qh, ql, 1024, 3072);
    // Attention -> bf16 hi/lo
    flash_attn<<<dim3(16, 32), blk, FLASH_SMEM>>>(qh, ql, ah, al);
    // Out: [4096,1024] = attn @ w_out^T -> fp32
    gemm_mma<false><<<dim3(1024 / 128, 4096 / 128), blk, GEMM_SMEM>>>(
        ah, al, woh, wol, out, nullptr, nullptr, 1024, 1024);
}

// round 12
// speedup vs baseline: 1.0824x; 1.0824x over previous
#include <cuda_runtime.h>
#include <cuda_bf16.h>
#include <math.h>
#include <stdint.h>

// ---------------------------------------------------------------------------
// Scratch (allocation-free rule: device globals)
// ---------------------------------------------------------------------------
__device__ __nv_bfloat16 g_xh[4096 * 1024],  g_xl[4096 * 1024];
__device__ __nv_bfloat16 g_wqh[3072 * 1024], g_wql[3072 * 1024];
__device__ __nv_bfloat16 g_woh[1024 * 1024], g_wol[1024 * 1024];
__device__ __nv_bfloat16 g_qh[4096 * 3072],  g_ql[4096 * 3072];   // qkv hi/lo
__device__ __nv_bfloat16 g_ah[4096 * 1024],  g_al[4096 * 1024];   // attn hi/lo

// ---------------------------------------------------------------------------
// Helpers
// ---------------------------------------------------------------------------
__device__ __forceinline__ uint32_t smem_u32(const void* p) {
    uint32_t a;
    asm("{ .reg .u64 t; cvta.to.shared.u64 t, %1; cvt.u32.u64 %0, t; }" : "=r"(a) : "l"(p));
    return a;
}
__device__ __forceinline__ float ex2(float x) {
    float r; asm("ex2.approx.f32 %0, %1;" : "=f"(r) : "f"(x)); return r;
}
// split two floats into packed bf16 hi-pair + lo-pair (x -> low half, y -> high)
__device__ __forceinline__ void split2(float x, float y, uint32_t& hi, uint32_t& lo) {
    uint32_t h;
    asm("cvt.rn.bf16x2.f32 %0, %1, %2;" : "=r"(h) : "f"(y), "f"(x));
    float hx = __uint_as_float(h << 16);
    float hy = __uint_as_float(h & 0xffff0000u);
    float lx = x - hx, ly = y - hy;
    uint32_t l;
    asm("cvt.rn.bf16x2.f32 %0, %1, %2;" : "=r"(l) : "f"(ly), "f"(lx));
    hi = h; lo = l;
}
__device__ __forceinline__ void split4(float4 v, uint2& hi, uint2& lo) {
    split2(v.x, v.y, hi.x, lo.x);
    split2(v.z, v.w, hi.y, lo.y);
}
__device__ __forceinline__ void mma_bf16(float c[4], const uint32_t a[4],
                                         uint32_t b0, uint32_t b1) {
    asm volatile(
        "mma.sync.aligned.m16n8k16.row.col.f32.bf16.bf16.f32 "
        "{%0,%1,%2,%3}, {%4,%5,%6,%7}, {%8,%9}, {%0,%1,%2,%3};"
        : "+f"(c[0]), "+f"(c[1]), "+f"(c[2]), "+f"(c[3])
        : "r"(a[0]), "r"(a[1]), "r"(a[2]), "r"(a[3]), "r"(b0), "r"(b1));
}
__device__ __forceinline__ void ldm_x4(uint32_t r[4], uint32_t addr) {
    asm volatile("ldmatrix.sync.aligned.m8n8.x4.shared.b16 {%0,%1,%2,%3}, [%4];"
                 : "=r"(r[0]), "=r"(r[1]), "=r"(r[2]), "=r"(r[3]) : "r"(addr));
}
__device__ __forceinline__ void ldm_x4_trans(uint32_t r[4], uint32_t addr) {
    asm volatile("ldmatrix.sync.aligned.m8n8.x4.trans.shared.b16 {%0,%1,%2,%3}, [%4];"
                 : "=r"(r[0]), "=r"(r[1]), "=r"(r[2]), "=r"(r[3]) : "r"(addr));
}
__device__ __forceinline__ void cp16(uint32_t saddr, const void* g) {
    asm volatile("cp.async.cg.shared.global [%0], [%1], 16;" :: "r"(saddr), "l"(g));
}
#define CP_COMMIT() asm volatile("cp.async.commit_group;" ::: "memory")
#define CP_WAIT1()  asm volatile("cp.async.wait_group 1;" ::: "memory")

// ---------------------------------------------------------------------------
// fused split kernel: all three fp32 inputs -> (hi, lo) bf16 arrays
// ---------------------------------------------------------------------------
#define X4 (4096 * 1024 / 4)
#define W4 (3072 * 1024 / 4)
#define O4 (1024 * 1024 / 4)

__global__ void split_all(const float* __restrict__ x,
                          const float* __restrict__ wq,
                          const float* __restrict__ wo,
                          __nv_bfloat16* __restrict__ xh, __nv_bfloat16* __restrict__ xl,
                          __nv_bfloat16* __restrict__ wqh, __nv_bfloat16* __restrict__ wql,
                          __nv_bfloat16* __restrict__ woh, __nv_bfloat16* __restrict__ wol) {
    int i = blockIdx.x * blockDim.x + threadIdx.x;
    float4 v;
    uint2 h, l;
    if (i < X4) {
        v = ((const float4*)x)[i];
        split4(v, h, l);
        ((uint2*)xh)[i] = h; ((uint2*)xl)[i] = l;
    } else if (i < X4 + W4) {
        int j = i - X4;
        v = ((const float4*)wq)[j];
        split4(v, h, l);
        ((uint2*)wqh)[j] = h; ((uint2*)wql)[j] = l;
    } else {
        int j = i - X4 - W4;
        v = ((const float4*)wo)[j];
        split4(v, h, l);
        ((uint2*)woh)[j] = h; ((uint2*)wol)[j] = l;
    }
}

// ---------------------------------------------------------------------------
// bf16x3 split GEMM: mma.sync + XOR-swizzled smem + 3-stage cp.async pipeline,
// ONE barrier per 32-K chunk, 2 CTAs/SM.
//   C[M,N] = A[M,K] @ B[N,K]^T;  epilogue: fp32 C  OR  bf16 hi/lo split pair.
// Layout: 64B rows (32 bf16), 4 chunks of 16B, phys_chunk = ch ^ ((row>>1)&3).
// ---------------------------------------------------------------------------
#define ARR_B  8192                  // 128 rows x 64 B
#define STG_B  (4 * ARR_B)           // Ah Al Bh Bl = 32768
#define NSTG   3
#define GEMM_SMEM (NSTG * STG_B)     // 98304 -> 2 CTAs/SM

template <bool SPLITC>
__global__ __launch_bounds__(256, 2) void gemm_mma(const __nv_bfloat16* __restrict__ Ahg,
                                                   const __nv_bfloat16* __restrict__ Alg,
                                                   const __nv_bfloat16* __restrict__ Bhg,
                                                   const __nv_bfloat16* __restrict__ Blg,
                                                   float* __restrict__ C,
                                                   __nv_bfloat16* __restrict__ Ch,
                                                   __nv_bfloat16* __restrict__ Cl,
                                                   int K, int N) {
    extern __shared__ __align__(16) char gsm[];
    const uint32_t sbase = smem_u32(gsm);

    const int tid = threadIdx.x;
    const int wid = tid >> 5;
    const int lane = tid & 31;
    const int wr = wid >> 2;
    const int wc = wid & 3;
    const int gr = lane >> 2, qq = lane & 3;
    const int row0 = blockIdx.y * 128;
    const int col0 = blockIdx.x * 128;
    const int NCH = K >> 5;

    // writer: 4 arrays x 128 rows x 4 chunks = 2048 cp16 -> 8 per thread
    auto load_chunk = [&](int kc, int stg) {
        const uint32_t st = sbase + stg * STG_B;
#pragma unroll
        for (int t = 0; t < 8; t++) {
            int idx = tid + t * 256;
            int arr = idx >> 9;
            int rem = idx & 511;
            int row = rem >> 2;
            int ch = rem & 3;
            uint32_t sa = st + arr * ARR_B + row * 64 + ((ch ^ ((row >> 1) & 3)) << 4);
            const __nv_bfloat16* gp;
            int kcol = kc * 32 + ch * 8;
            if (arr == 0)      gp = &Ahg[(size_t)(row0 + row) * K + kcol];
            else if (arr == 1) gp = &Alg[(size_t)(row0 + row) * K + kcol];
            else if (arr == 2) gp = &Bhg[(size_t)(col0 + row) * K + kcol];
            else               gp = &Blg[(size_t)(col0 + row) * K + kcol];
            cp16(sa, gp);
        }
    };

    float acc[4][4][4] = {};

    load_chunk(0, 0);
    CP_COMMIT();
    load_chunk(1, 1);
    CP_COMMIT();

    // per-lane ldmatrix addressing
    const uint32_t lrow = lane & 15;
    const int kbase = lane >> 4;               // chunk low bit (0/1)
    const uint32_t sw = (lrow >> 1) & 3;       // row-swizzle (tile rows are mult of 16)
    uint32_t aoff[4], boff[2];
#pragma unroll
    for (int i = 0; i < 4; i++) aoff[i] = (wr * 64 + i * 16 + lrow) * 64;
#pragma unroll
    for (int g = 0; g < 2; g++) boff[g] = (wc * 32 + g * 16 + lrow) * 64;

    for (int c = 0; c < NCH; c++) {
        CP_WAIT1();            // chunk c landed (c+1 may still fly)
        __syncthreads();       // all warps done with stage (c+2)%3's old contents
        int nc = c + 2;
        if (nc < NCH) load_chunk(nc, nc % 3);
        CP_COMMIT();

        const uint32_t st = sbase + (c % 3) * STG_B;
        const uint32_t ah = st, al = st + ARR_B, bh = st + 2 * ARR_B, bl = st + 3 * ARR_B;
#pragma unroll
        for (int ks = 0; ks < 2; ks++) {
            const uint32_t scol = (uint32_t)(((ks * 2 + kbase) ^ sw) << 4);
            // --- term 1: Ah * Bh ---
            uint32_t fa[4][4], fb[4][2];
#pragma unroll
            for (int i = 0; i < 4; i++)
                ldm_x4(fa[i], ah + aoff[i] + scol);
#pragma unroll
            for (int g = 0; g < 2; g++) {
                uint32_t r[4];
                ldm_x4(r, bh + boff[g] + scol);
                fb[2 * g][0] = r[0]; fb[2 * g][1] = r[2];
                fb[2 * g + 1][0] = r[1]; fb[2 * g + 1][1] = r[3];
            }
#pragma unroll
            for (int i = 0; i < 4; i++)
#pragma unroll
                for (int j = 0; j < 4; j++)
                    mma_bf16(acc[i][j], fa[i], fb[j][0], fb[j][1]);
            // --- term 2: Ah * Bl ---
            uint32_t fbl[4][2];
#pragma unroll
            for (int g = 0; g < 2; g++) {
                uint32_t r[4];
                ldm_x4(r, bl + boff[g] + scol);
                fbl[2 * g][0] = r[0]; fbl[2 * g][1] = r[2];
                fbl[2 * g + 1][0] = r[1]; fbl[2 * g + 1][1] = r[3];
            }
#pragma unroll
            for (int i = 0; i < 4; i++)
#pragma unroll
                for (int j = 0; j < 4; j++)
                    mma_bf16(acc[i][j], fa[i], fbl[j][0], fbl[j][1]);
            // --- term 3: Al * Bh ---
#pragma unroll
            for (int i = 0; i < 4; i++)
                ldm_x4(fa[i], al + aoff[i] + scol);
#pragma unroll
            for (int i = 0; i < 4; i++)
#pragma unroll
                for (int j = 0; j < 4; j++)
                    mma_bf16(acc[i][j], fa[i], fb[j][0], fb[j][1]);
        }
    }

    // epilogue
#pragma unroll
    for (int i = 0; i < 4; i++) {
        int r0g = row0 + wr * 64 + i * 16 + gr;
#pragma unroll
        for (int j = 0; j < 4; j++) {
            int cg = col0 + wc * 32 + j * 8 + 2 * qq;
            if (SPLITC) {
                uint32_t hi, lo;
                split2(acc[i][j][0], acc[i][j][1], hi, lo);
                *(uint32_t*)&Ch[(size_t)r0g * N + cg] = hi;
                *(uint32_t*)&Cl[(size_t)r0g * N + cg] = lo;
                split2(acc[i][j][2], acc[i][j][3], hi, lo);
                *(uint32_t*)&Ch[(size_t)(r0g + 8) * N + cg] = hi;
                *(uint32_t*)&Cl[(size_t)(r0g + 8) * N + cg] = lo;
            } else {
                *(float2*)&C[(size_t)r0g * N + cg] = make_float2(acc[i][j][0], acc[i][j][1]);
                *(float2*)&C[(size_t)(r0g + 8) * N + cg] = make_float2(acc[i][j][2], acc[i][j][3]);
            }
        }
    }
}

// ---------------------------------------------------------------------------
// Flash attention on tensor cores, bf16 hi/lo in/out, cp.async double-buffer.
// CTA: 128 q-rows x one (b,h); 8 warps x 16 q-rows; 32 key-tiles of 64.
// (unchanged from R11)
// ---------------------------------------------------------------------------
#define FP     72                       // bf16 row pitch (144 B)
#define FQ_B   (128 * FP * 2)           // Q array bytes (18432)
#define KV_B   (64 * FP * 2)            // KV array bytes (9216)
#define KVS_B  (4 * KV_B)               // KV stage bytes (36864)
#define FLASH_SMEM (2 * FQ_B + 2 * KVS_B)   // 110592

__global__ __launch_bounds__(256, 2) void flash_attn(const __nv_bfloat16* __restrict__ qh,
                                                     const __nv_bfloat16* __restrict__ ql,
                                                     __nv_bfloat16* __restrict__ oh,
                                                     __nv_bfloat16* __restrict__ ol) {
    extern __shared__ __align__(16) char fsmc[];
    const uint32_t sb = smem_u32(fsmc);
    __nv_bfloat16* Qh = (__nv_bfloat16*)fsmc;

    const int tid = threadIdx.x;
    const int wid = tid >> 5;
    const int lane = tid & 31;
    const int gr = lane >> 2;
    const int qq = lane & 3;

    const int qt = blockIdx.x;
    const int b  = blockIdx.y >> 4;
    const int h  = blockIdx.y & 15;

    const size_t tok0 = (size_t)b * 2048;
    const int qoff = h * 64, koff = 1024 + h * 64, voff = 2048 + h * 64;
    const float QS = 0.125f * 1.4426950408889634f;   // 1/sqrt(64) * log2(e)

    // ---- async load Q (2 arrays x 128 rows x 8 chunks) ----
#pragma unroll
    for (int i = 0; i < 8; i++) {
        int idx = tid + i * 256;
        int arr = idx >> 10;
        int rem = idx & 1023;
        int row = rem >> 3, ch = rem & 7;
        const __nv_bfloat16* src = (arr ? ql : qh) +
            (tok0 + qt * 128 + row) * 3072 + qoff + ch * 8;
        cp16(sb + arr * FQ_B + row * 144 + ch * 16, src);
    }
    auto load_kv = [&](int kt, int s) {
        const uint32_t st = sb + 2 * FQ_B + s * KVS_B;
#pragma unroll
        for (int i = 0; i < 8; i++) {
            int idx = tid + i * 256;
            int arr = idx >> 9;
            int rem = idx & 511;
            int row = rem >> 3, ch = rem & 7;
            int gcol = (arr < 2 ? koff : voff) + ch * 8;
            const __nv_bfloat16* src = ((arr & 1) ? ql : qh) +
                (tok0 + kt * 64 + row) * 3072 + gcol;
            cp16(st + arr * KV_B + row * 144 + ch * 16, src);
        }
    };

    load_kv(0, 0);
    CP_COMMIT();
    load_kv(1, 1);
    CP_COMMIT();
    CP_WAIT1();
    __syncthreads();

    uint32_t qa_h[4][4];
    const int qrow = wid * 16;
    const uint32_t ql_u = sb + FQ_B;
    const uint32_t lrow16 = lane & 15;
    const uint32_t lcol8 = (lane >> 4) << 3;
    const uint32_t qfrag_off = (qrow + lrow16) * 144 + lcol8 * 2;
#pragma unroll
    for (int kap = 0; kap < 4; kap++) {
        int cb = kap * 16 + 2 * qq;
        qa_h[kap][0] = *(const uint32_t*)&Qh[(qrow + gr) * FP + cb];
        qa_h[kap][1] = *(const uint32_t*)&Qh[(qrow + gr + 8) * FP + cb];
        qa_h[kap][2] = *(const uint32_t*)&Qh[(qrow + gr) * FP + cb + 8];
        qa_h[kap][3] = *(const uint32_t*)&Qh[(qrow + gr + 8) * FP + cb + 8];
    }

    float m0 = -1e30f, m1 = -1e30f, l0 = 0.0f, l1 = 0.0f;
    float o[8][4] = {};

    for (int kt = 0; kt < 32; kt++) {
        const uint32_t st = sb + 2 * FQ_B + (kt & 1) * KVS_B;
        const uint32_t kh_u = st;
        const uint32_t kl_u = st + KV_B;
        const uint32_t vh_u = st + 2 * KV_B;
        const uint32_t vl_u = st + 3 * KV_B;

        float S[8][4];
#pragma unroll
        for (int j = 0; j < 8; j++) { S[j][0] = S[j][1] = S[j][2] = S[j][3] = 0.0f; }
#pragma unroll
        for (int kap = 0; kap < 4; kap++) {
            uint32_t qa_l[4];
            ldm_x4(qa_l, ql_u + qfrag_off + kap * 32);
            const uint32_t koff2 = (kap * 16 + lcol8) * 2;
#pragma unroll
            for (int jp = 0; jp < 4; jp++) {
                uint32_t rh[4], rl[4];
                const uint32_t rowa = (jp * 16 + lrow16) * 144 + koff2;
                ldm_x4(rh, kh_u + rowa);
                ldm_x4(rl, kl_u + rowa);
                mma_bf16(S[2 * jp],     qa_h[kap], rh[0], rh[2]);
                mma_bf16(S[2 * jp + 1], qa_h[kap], rh[1], rh[3]);
                mma_bf16(S[2 * jp],     qa_h[kap], rl[0], rl[2]);
                mma_bf16(S[2 * jp + 1], qa_h[kap], rl[1], rl[3]);
                mma_bf16(S[2 * jp],     qa_l, rh[0], rh[2]);
                mma_bf16(S[2 * jp + 1], qa_l, rh[1], rh[3]);
            }
        }
#pragma unroll
        for (int j = 0; j < 8; j++) {
            S[j][0] *= QS; S[j][1] *= QS; S[j][2] *= QS; S[j][3] *= QS;
        }

        float t0 = -1e30f, t1 = -1e30f;
#pragma unroll
        for (int j = 0; j < 8; j++) {
            t0 = fmaxf(t0, fmaxf(S[j][0], S[j][1]));
            t1 = fmaxf(t1, fmaxf(S[j][2], S[j][3]));
        }
        t0 = fmaxf(t0, __shfl_xor_sync(0xffffffffu, t0, 1));
        t0 = fmaxf(t0, __shfl_xor_sync(0xffffffffu, t0, 2));
        t1 = fmaxf(t1, __shfl_xor_sync(0xffffffffu, t1, 1));
        t1 = fmaxf(t1, __shfl_xor_sync(0xffffffffu, t1, 2));
        float mn0 = fmaxf(m0, t0), mn1 = fmaxf(m1, t1);
        float al0 = ex2(m0 - mn0), al1 = ex2(m1 - mn1);
        m0 = mn0; m1 = mn1;

        float rs0 = 0.0f, rs1 = 0.0f;
#pragma unroll
        for (int j = 0; j < 8; j++) {
            S[j][0] = ex2(S[j][0] - m0);
            S[j][1] = ex2(S[j][1] - m0);
            S[j][2] = ex2(S[j][2] - m1);
            S[j][3] = ex2(S[j][3] - m1);
            rs0 += S[j][0] + S[j][1];
            rs1 += S[j][2] + S[j][3];
        }
        rs0 += __shfl_xor_sync(0xffffffffu, rs0, 1);
        rs0 += __shfl_xor_sync(0xffffffffu, rs0, 2);
        rs1 += __shfl_xor_sync(0xffffffffu, rs1, 1);
        rs1 += __shfl_xor_sync(0xffffffffu, rs1, 2);
        l0 = l0 * al0 + rs0;
        l1 = l1 * al1 + rs1;
#pragma unroll
        for (int jn = 0; jn < 8; jn++) {
            o[jn][0] *= al0; o[jn][1] *= al0;
            o[jn][2] *= al1; o[jn][3] *= al1;
        }

        uint32_t ph[4][4], pl[4][4];
#pragma unroll
        for (int kap = 0; kap < 4; kap++) {
            const float* s0 = S[2 * kap];
            const float* s1 = S[2 * kap + 1];
            split2(s0[0], s0[1], ph[kap][0], pl[kap][0]);
            split2(s0[2], s0[3], ph[kap][1], pl[kap][1]);
            split2(s1[0], s1[1], ph[kap][2], pl[kap][2]);
            split2(s1[2], s1[3], ph[kap][3], pl[kap][3]);
        }

#pragma unroll
        for (int jn = 0; jn < 8; jn++) {
#pragma unroll
            for (int kp2 = 0; kp2 < 2; kp2++) {
                uint32_t vh4[4], vl4[4];
                const uint32_t rowa = (kp2 * 32 + lane) * 144 + jn * 16;
                ldm_x4_trans(vh4, vh_u + rowa);
                ldm_x4_trans(vl4, vl_u + rowa);
                mma_bf16(o[jn], ph[2 * kp2],     vh4[0], vh4[1]);
                mma_bf16(o[jn], ph[2 * kp2],     vl4[0], vl4[1]);
                mma_bf16(o[jn], pl[2 * kp2],     vh4[0], vh4[1]);
                mma_bf16(o[jn], ph[2 * kp2 + 1], vh4[2], vh4[3]);
                mma_bf16(o[jn], ph[2 * kp2 + 1], vl4[2], vl4[3]);
                mma_bf16(o[jn], pl[2 * kp2 + 1], vh4[2], vh4[3]);
            }
        }

        __syncthreads();
        if (kt + 2 < 32) load_kv(kt + 2, kt & 1);
        CP_COMMIT();
        if (kt + 1 < 32) {
            CP_WAIT1();
            __syncthreads();
        }
    }

    float inv0 = 1.0f / l0, inv1 = 1.0f / l1;
    const size_t row0 = (tok0 + qt * 128 + wid * 16 + gr) * 1024 + h * 64;
    const size_t row1 = row0 + 8 * 1024;
#pragma unroll
    for (int jn = 0; jn < 8; jn++) {
        int cc = jn * 8 + 2 * qq;
        uint32_t hi, lo;
        split2(o[jn][0] * inv0, o[jn][1] * inv0, hi, lo);
        *(uint32_t*)&oh[row0 + cc] = hi;
        *(uint32_t*)&ol[row0 + cc] = lo;
        split2(o[jn][2] * inv1, o[jn][3] * inv1, hi, lo);
        *(uint32_t*)&oh[row1 + cc] = hi;
        *(uint32_t*)&ol[row1 + cc] = lo;
    }
}

// ---------------------------------------------------------------------------
// Launch: fused split -> QKV GEMM (split out) -> flash (split out) -> out GEMM
// ---------------------------------------------------------------------------
extern "C" void kernel_launch(void* const* d_in, const int* in_sizes, int n_in,
                              void* d_out, int out_size) {
    const float* x     = (const float*)d_in[0];  // [2,2048,1024]
    const float* w_qkv = (const float*)d_in[1];  // [3072,1024]
    const float* w_out = (const float*)d_in[2];  // [1024,1024]
    float* out = (float*)d_out;                  // [2,2048,1024]

    __nv_bfloat16 *xh, *xl, *wqh, *wql, *woh, *wol, *qh, *ql, *ah, *al;
    cudaGetSymbolAddress((void**)&xh, g_xh);   cudaGetSymbolAddress((void**)&xl, g_xl);
    cudaGetSymbolAddress((void**)&wqh, g_wqh); cudaGetSymbolAddress((void**)&wql, g_wql);
    cudaGetSymbolAddress((void**)&woh, g_woh); cudaGetSymbolAddress((void**)&wol, g_wol);
    cudaGetSymbolAddress((void**)&qh, g_qh);   cudaGetSymbolAddress((void**)&ql, g_ql);
    cudaGetSymbolAddress((void**)&ah, g_ah);   cudaGetSymbolAddress((void**)&al, g_al);

    cudaFuncSetAttribute(flash_attn, cudaFuncAttributeMaxDynamicSharedMemorySize, FLASH_SMEM);
    cudaFuncSetAttribute(gemm_mma<true>, cudaFuncAttributeMaxDynamicSharedMemorySize, GEMM_SMEM);
    cudaFuncSetAttribute(gemm_mma<false>, cudaFuncAttributeMaxDynamicSharedMemorySize, GEMM_SMEM);

    dim3 blk(256);
    split_all<<<(X4 + W4 + O4) / 256, blk>>>(x, w_qkv, w_out, xh, xl, wqh, wql, woh, wol);
    // QKV: [4096,3072] = x @ w_qkv^T  -> bf16 hi/lo
    gemm_mma<true><<<dim3(3072 / 128, 4096 / 128), blk, GEMM_SMEM>>>(
        xh, xl, wqh, wql, nullptr, qh, ql, 1024, 3072);
    // Attention -> bf16 hi/lo
    flash_attn<<<dim3(16, 32), blk, FLASH_SMEM>>>(qh, ql, ah, al);
    // Out: [4096,1024] = attn @ w_out^T -> fp32
    gemm_mma<false><<<dim3(1024 / 128, 4096 / 128), blk, GEMM_SMEM>>>(
        ah, al, woh, wol, out, nullptr, nullptr, 1024, 1024);
}

// round 13
// speedup vs baseline: 1.2533x; 1.1579x over previous
#include <cuda_runtime.h>
#include <cuda_fp16.h>
#include <math.h>
#include <stdint.h>

// ---------------------------------------------------------------------------
// Scratch (allocation-free rule: device globals)  — all fp16 now
// ---------------------------------------------------------------------------
__device__ __half g_xh[4096 * 1024],  g_xl[4096 * 1024];   // x hi/lo
__device__ __half g_wq[3072 * 1024];                       // w_qkv single fp16
__device__ __half g_wo[1024 * 1024];                       // w_out single fp16
__device__ __half g_qh[4096 * 3072],  g_ql[4096 * 3072];   // qkv hi/lo
__device__ __half g_ah[4096 * 1024],  g_al[4096 * 1024];   // attn hi/lo

// ---------------------------------------------------------------------------
// Helpers
// ---------------------------------------------------------------------------
__device__ __forceinline__ uint32_t smem_u32(const void* p) {
    uint32_t a;
    asm("{ .reg .u64 t; cvta.to.shared.u64 t, %1; cvt.u32.u64 %0, t; }" : "=r"(a) : "l"(p));
    return a;
}
__device__ __forceinline__ float ex2(float x) {
    float r; asm("ex2.approx.f32 %0, %1;" : "=f"(r) : "f"(x)); return r;
}
// pack two floats to f16x2 (x -> low half)
__device__ __forceinline__ uint32_t packh(float x, float y) {
    uint32_t h;
    asm("cvt.rn.f16x2.f32 %0, %1, %2;" : "=r"(h) : "f"(y), "f"(x));
    return h;
}
// split two floats into packed f16 hi-pair + lo-pair
__device__ __forceinline__ void split2h(float x, float y, uint32_t& hi, uint32_t& lo) {
    uint32_t h = packh(x, y);
    __half2 h2 = *(__half2*)&h;
    float2 f = __half22float2(h2);
    hi = h;
    lo = packh(x - f.x, y - f.y);
}
__device__ __forceinline__ void split4h(float4 v, uint2& hi, uint2& lo) {
    split2h(v.x, v.y, hi.x, lo.x);
    split2h(v.z, v.w, hi.y, lo.y);
}
__device__ __forceinline__ void mma_f16(float c[4], const uint32_t a[4],
                                        uint32_t b0, uint32_t b1) {
    asm volatile(
        "mma.sync.aligned.m16n8k16.row.col.f32.f16.f16.f32 "
        "{%0,%1,%2,%3}, {%4,%5,%6,%7}, {%8,%9}, {%0,%1,%2,%3};"
        : "+f"(c[0]), "+f"(c[1]), "+f"(c[2]), "+f"(c[3])
        : "r"(a[0]), "r"(a[1]), "r"(a[2]), "r"(a[3]), "r"(b0), "r"(b1));
}
__device__ __forceinline__ void ldm_x4(uint32_t r[4], uint32_t addr) {
    asm volatile("ldmatrix.sync.aligned.m8n8.x4.shared.b16 {%0,%1,%2,%3}, [%4];"
                 : "=r"(r[0]), "=r"(r[1]), "=r"(r[2]), "=r"(r[3]) : "r"(addr));
}
__device__ __forceinline__ void ldm_x4_trans(uint32_t r[4], uint32_t addr) {
    asm volatile("ldmatrix.sync.aligned.m8n8.x4.trans.shared.b16 {%0,%1,%2,%3}, [%4];"
                 : "=r"(r[0]), "=r"(r[1]), "=r"(r[2]), "=r"(r[3]) : "r"(addr));
}
__device__ __forceinline__ void cp16(uint32_t saddr, const void* g) {
    asm volatile("cp.async.cg.shared.global [%0], [%1], 16;" :: "r"(saddr), "l"(g));
}
#define CP_COMMIT() asm volatile("cp.async.commit_group;" ::: "memory")
#define CP_WAIT1()  asm volatile("cp.async.wait_group 1;" ::: "memory")

// ---------------------------------------------------------------------------
// fused split kernel: x -> fp16 hi/lo;  w_qkv, w_out -> single fp16
// ---------------------------------------------------------------------------
#define X4 (4096 * 1024 / 4)
#define W4 (3072 * 1024 / 4)
#define O4 (1024 * 1024 / 4)

__global__ void split_all(const float* __restrict__ x,
                          const float* __restrict__ wq,
                          const float* __restrict__ wo,
                          __half* __restrict__ xh, __half* __restrict__ xl,
                          __half* __restrict__ wqh, __half* __restrict__ woh) {
    int i = blockIdx.x * blockDim.x + threadIdx.x;
    if (i < X4) {
        float4 v = ((const float4*)x)[i];
        uint2 h, l;
        split4h(v, h, l);
        ((uint2*)xh)[i] = h; ((uint2*)xl)[i] = l;
    } else if (i < X4 + W4) {
        int j = i - X4;
        float4 v = ((const float4*)wq)[j];
        uint2 h;
        h.x = packh(v.x, v.y); h.y = packh(v.z, v.w);
        ((uint2*)wqh)[j] = h;
    } else {
        int j = i - X4 - W4;
        float4 v = ((const float4*)wo)[j];
        uint2 h;
        h.x = packh(v.x, v.y); h.y = packh(v.z, v.w);
        ((uint2*)woh)[j] = h;
    }
}

// ---------------------------------------------------------------------------
// fp16 asymmetric 2-term GEMM:  C = (Ah + Al) @ B^T,  B single fp16.
// mma.sync + XOR-swizzled smem + 3-stage cp.async, one barrier/chunk, 2 CTA/SM.
// ---------------------------------------------------------------------------
#define ARR_B  8192                  // 128 rows x 64 B (32 fp16)
#define STG_B  (3 * ARR_B)           // Ah Al B = 24576
#define NSTG   3
#define GEMM_SMEM (NSTG * STG_B)     // 73728 -> 2 CTAs/SM

template <bool SPLITC>
__global__ __launch_bounds__(256, 2) void gemm_mma(const __half* __restrict__ Ahg,
                                                   const __half* __restrict__ Alg,
                                                   const __half* __restrict__ Bg,
                                                   float* __restrict__ C,
                                                   __half* __restrict__ Ch,
                                                   __half* __restrict__ Cl,
                                                   int K, int N) {
    extern __shared__ __align__(16) char gsm[];
    const uint32_t sbase = smem_u32(gsm);

    const int tid = threadIdx.x;
    const int wid = tid >> 5;
    const int lane = tid & 31;
    const int wr = wid >> 2;
    const int wc = wid & 3;
    const int gr = lane >> 2, qq = lane & 3;
    const int row0 = blockIdx.y * 128;
    const int col0 = blockIdx.x * 128;
    const int NCH = K >> 5;

    // writer: 3 arrays x 128 rows x 4 chunks = 1536 cp16 -> 6 per thread
    auto load_chunk = [&](int kc, int stg) {
        const uint32_t st = sbase + stg * STG_B;
#pragma unroll
        for (int t = 0; t < 6; t++) {
            int idx = tid + t * 256;
            int arr = idx >> 9;
            int rem = idx & 511;
            int row = rem >> 2;
            int ch = rem & 3;
            uint32_t sa = st + arr * ARR_B + row * 64 + ((ch ^ ((row >> 1) & 3)) << 4);
            const __half* gp;
            int kcol = kc * 32 + ch * 8;
            if (arr == 0)      gp = &Ahg[(size_t)(row0 + row) * K + kcol];
            else if (arr == 1) gp = &Alg[(size_t)(row0 + row) * K + kcol];
            else               gp = &Bg[(size_t)(col0 + row) * K + kcol];
            cp16(sa, gp);
        }
    };

    float acc[4][4][4] = {};

    load_chunk(0, 0);
    CP_COMMIT();
    load_chunk(1, 1);
    CP_COMMIT();

    const uint32_t lrow = lane & 15;
    const int kbase = lane >> 4;
    const uint32_t sw = (lrow >> 1) & 3;
    uint32_t aoff[4], boff[2];
#pragma unroll
    for (int i = 0; i < 4; i++) aoff[i] = (wr * 64 + i * 16 + lrow) * 64;
#pragma unroll
    for (int g = 0; g < 2; g++) boff[g] = (wc * 32 + g * 16 + lrow) * 64;

    for (int c = 0; c < NCH; c++) {
        CP_WAIT1();
        __syncthreads();
        int nc = c + 2;
        if (nc < NCH) load_chunk(nc, nc % 3);
        CP_COMMIT();

        const uint32_t st = sbase + (c % 3) * STG_B;
        const uint32_t ah = st, al = st + ARR_B, bh = st + 2 * ARR_B;
#pragma unroll
        for (int ks = 0; ks < 2; ks++) {
            const uint32_t scol = (uint32_t)(((ks * 2 + kbase) ^ sw) << 4);
            // --- term 1: Ah * B ---
            uint32_t fa[4][4], fb[4][2];
#pragma unroll
            for (int i = 0; i < 4; i++)
                ldm_x4(fa[i], ah + aoff[i] + scol);
#pragma unroll
            for (int g = 0; g < 2; g++) {
                uint32_t r[4];
                ldm_x4(r, bh + boff[g] + scol);
                fb[2 * g][0] = r[0]; fb[2 * g][1] = r[2];
                fb[2 * g + 1][0] = r[1]; fb[2 * g + 1][1] = r[3];
            }
#pragma unroll
            for (int i = 0; i < 4; i++)
#pragma unroll
                for (int j = 0; j < 4; j++)
                    mma_f16(acc[i][j], fa[i], fb[j][0], fb[j][1]);
            // --- term 2: Al * B ---
#pragma unroll
            for (int i = 0; i < 4; i++)
                ldm_x4(fa[i], al + aoff[i] + scol);
#pragma unroll
            for (int i = 0; i < 4; i++)
#pragma unroll
                for (int j = 0; j < 4; j++)
                    mma_f16(acc[i][j], fa[i], fb[j][0], fb[j][1]);
        }
    }

    // epilogue
#pragma unroll
    for (int i = 0; i < 4; i++) {
        int r0g = row0 + wr * 64 + i * 16 + gr;
#pragma unroll
        for (int j = 0; j < 4; j++) {
            int cg = col0 + wc * 32 + j * 8 + 2 * qq;
            if (SPLITC) {
                uint32_t hi, lo;
                split2h(acc[i][j][0], acc[i][j][1], hi, lo);
                *(uint32_t*)&Ch[(size_t)r0g * N + cg] = hi;
                *(uint32_t*)&Cl[(size_t)r0g * N + cg] = lo;
                split2h(acc[i][j][2], acc[i][j][3], hi, lo);
                *(uint32_t*)&Ch[(size_t)(r0g + 8) * N + cg] = hi;
                *(uint32_t*)&Cl[(size_t)(r0g + 8) * N + cg] = lo;
            } else {
                *(float2*)&C[(size_t)r0g * N + cg] = make_float2(acc[i][j][0], acc[i][j][1]);
                *(float2*)&C[(size_t)(r0g + 8) * N + cg] = make_float2(acc[i][j][2], acc[i][j][3]);
            }
        }
    }
}

// ---------------------------------------------------------------------------
// Flash attention on tensor cores, fp16 hi/lo in/out (3-term, high precision),
// cp.async double-buffer. CTA: 128 q-rows x (b,h); 8 warps; 32 key-tiles of 64.
// ---------------------------------------------------------------------------
#define FP     72                       // fp16 row pitch (144 B)
#define FQ_B   (128 * FP * 2)           // Q array bytes (18432)
#define KV_B   (64 * FP * 2)            // KV array bytes (9216)
#define KVS_B  (4 * KV_B)               // KV stage bytes (36864)
#define FLASH_SMEM (2 * FQ_B + 2 * KVS_B)   // 110592

__global__ __launch_bounds__(256, 2) void flash_attn(const __half* __restrict__ qh,
                                                     const __half* __restrict__ ql,
                                                     __half* __restrict__ oh,
                                                     __half* __restrict__ ol) {
    extern __shared__ __align__(16) char fsmc[];
    const uint32_t sb = smem_u32(fsmc);
    __half* Qh = (__half*)fsmc;

    const int tid = threadIdx.x;
    const int wid = tid >> 5;
    const int lane = tid & 31;
    const int gr = lane >> 2;
    const int qq = lane & 3;

    const int qt = blockIdx.x;
    const int b  = blockIdx.y >> 4;
    const int h  = blockIdx.y & 15;

    const size_t tok0 = (size_t)b * 2048;
    const int qoff = h * 64, koff = 1024 + h * 64, voff = 2048 + h * 64;
    const float QS = 0.125f * 1.4426950408889634f;   // 1/sqrt(64) * log2(e)

#pragma unroll
    for (int i = 0; i < 8; i++) {
        int idx = tid + i * 256;
        int arr = idx >> 10;
        int rem = idx & 1023;
        int row = rem >> 3, ch = rem & 7;
        const __half* src = (arr ? ql : qh) +
            (tok0 + qt * 128 + row) * 3072 + qoff + ch * 8;
        cp16(sb + arr * FQ_B + row * 144 + ch * 16, src);
    }
    auto load_kv = [&](int kt, int s) {
        const uint32_t st = sb + 2 * FQ_B + s * KVS_B;
#pragma unroll
        for (int i = 0; i < 8; i++) {
            int idx = tid + i * 256;
            int arr = idx >> 9;
            int rem = idx & 511;
            int row = rem >> 3, ch = rem & 7;
            int gcol = (arr < 2 ? koff : voff) + ch * 8;
            const __half* src = ((arr & 1) ? ql : qh) +
                (tok0 + kt * 64 + row) * 3072 + gcol;
            cp16(st + arr * KV_B + row * 144 + ch * 16, src);
        }
    };

    load_kv(0, 0);
    CP_COMMIT();
    load_kv(1, 1);
    CP_COMMIT();
    CP_WAIT1();
    __syncthreads();

    uint32_t qa_h[4][4];
    const int qrow = wid * 16;
    const uint32_t ql_u = sb + FQ_B;
    const uint32_t lrow16 = lane & 15;
    const uint32_t lcol8 = (lane >> 4) << 3;
    const uint32_t qfrag_off = (qrow + lrow16) * 144 + lcol8 * 2;
#pragma unroll
    for (int kap = 0; kap < 4; kap++) {
        int cb = kap * 16 + 2 * qq;
        qa_h[kap][0] = *(const uint32_t*)&Qh[(qrow + gr) * FP + cb];
        qa_h[kap][1] = *(const uint32_t*)&Qh[(qrow + gr + 8) * FP + cb];
        qa_h[kap][2] = *(const uint32_t*)&Qh[(qrow + gr) * FP + cb + 8];
        qa_h[kap][3] = *(const uint32_t*)&Qh[(qrow + gr + 8) * FP + cb + 8];
    }

    float m0 = -1e30f, m1 = -1e30f, l0 = 0.0f, l1 = 0.0f;
    float o[8][4] = {};

    for (int kt = 0; kt < 32; kt++) {
        const uint32_t st = sb + 2 * FQ_B + (kt & 1) * KVS_B;
        const uint32_t kh_u = st;
        const uint32_t kl_u = st + KV_B;
        const uint32_t vh_u = st + 2 * KV_B;
        const uint32_t vl_u = st + 3 * KV_B;
        const __half* Kh = (const __half*)(fsmc + 2 * FQ_B + (kt & 1) * KVS_B);
        const __half* Kl = Kh + 64 * FP;
        (void)Kh; (void)Kl;

        float S[8][4];
#pragma unroll
        for (int j = 0; j < 8; j++) { S[j][0] = S[j][1] = S[j][2] = S[j][3] = 0.0f; }
#pragma unroll
        for (int kap = 0; kap < 4; kap++) {
            uint32_t qa_l[4];
            ldm_x4(qa_l, ql_u + qfrag_off + kap * 32);
            const uint32_t koff2 = (kap * 16 + lcol8) * 2;
#pragma unroll
            for (int jp = 0; jp < 4; jp++) {
                uint32_t rh[4], rl[4];
                const uint32_t rowa = (jp * 16 + lrow16) * 144 + koff2;
                ldm_x4(rh, kh_u + rowa);
                ldm_x4(rl, kl_u + rowa);
                mma_f16(S[2 * jp],     qa_h[kap], rh[0], rh[2]);
                mma_f16(S[2 * jp + 1], qa_h[kap], rh[1], rh[3]);
                mma_f16(S[2 * jp],     qa_h[kap], rl[0], rl[2]);
                mma_f16(S[2 * jp + 1], qa_h[kap], rl[1], rl[3]);
                mma_f16(S[2 * jp],     qa_l, rh[0], rh[2]);
                mma_f16(S[2 * jp + 1], qa_l, rh[1], rh[3]);
            }
        }
#pragma unroll
        for (int j = 0; j < 8; j++) {
            S[j][0] *= QS; S[j][1] *= QS; S[j][2] *= QS; S[j][3] *= QS;
        }

        float t0 = -1e30f, t1 = -1e30f;
#pragma unroll
        for (int j = 0; j < 8; j++) {
            t0 = fmaxf(t0, fmaxf(S[j][0], S[j][1]));
            t1 = fmaxf(t1, fmaxf(S[j][2], S[j][3]));
        }
        t0 = fmaxf(t0, __shfl_xor_sync(0xffffffffu, t0, 1));
        t0 = fmaxf(t0, __shfl_xor_sync(0xffffffffu, t0, 2));
        t1 = fmaxf(t1, __shfl_xor_sync(0xffffffffu, t1, 1));
        t1 = fmaxf(t1, __shfl_xor_sync(0xffffffffu, t1, 2));
        float mn0 = fmaxf(m0, t0), mn1 = fmaxf(m1, t1);
        float al0 = ex2(m0 - mn0), al1 = ex2(m1 - mn1);
        m0 = mn0; m1 = mn1;

        float rs0 = 0.0f, rs1 = 0.0f;
#pragma unroll
        for (int j = 0; j < 8; j++) {
            S[j][0] = ex2(S[j][0] - m0);
            S[j][1] = ex2(S[j][1] - m0);
            S[j][2] = ex2(S[j][2] - m1);
            S[j][3] = ex2(S[j][3] - m1);
            rs0 += S[j][0] + S[j][1];
            rs1 += S[j][2] + S[j][3];
        }
        rs0 += __shfl_xor_sync(0xffffffffu, rs0, 1);
        rs0 += __shfl_xor_sync(0xffffffffu, rs0, 2);
        rs1 += __shfl_xor_sync(0xffffffffu, rs1, 1);
        rs1 += __shfl_xor_sync(0xffffffffu, rs1, 2);
        l0 = l0 * al0 + rs0;
        l1 = l1 * al1 + rs1;
#pragma unroll
        for (int jn = 0; jn < 8; jn++) {
            o[jn][0] *= al0; o[jn][1] *= al0;
            o[jn][2] *= al1; o[jn][3] *= al1;
        }

        uint32_t ph[4][4], pl[4][4];
#pragma unroll
        for (int kap = 0; kap < 4; kap++) {
            const float* s0 = S[2 * kap];
            const float* s1 = S[2 * kap + 1];
            split2h(s0[0], s0[1], ph[kap][0], pl[kap][0]);
            split2h(s0[2], s0[3], ph[kap][1], pl[kap][1]);
            split2h(s1[0], s1[1], ph[kap][2], pl[kap][2]);
            split2h(s1[2], s1[3], ph[kap][3], pl[kap][3]);
        }

#pragma unroll
        for (int jn = 0; jn < 8; jn++) {
#pragma unroll
            for (int kp2 = 0; kp2 < 2; kp2++) {
                uint32_t vh4[4], vl4[4];
                const uint32_t rowa = (kp2 * 32 + lane) * 144 + jn * 16;
                ldm_x4_trans(vh4, vh_u + rowa);
                ldm_x4_trans(vl4, vl_u + rowa);
                mma_f16(o[jn], ph[2 * kp2],     vh4[0], vh4[1]);
                mma_f16(o[jn], ph[2 * kp2],     vl4[0], vl4[1]);
                mma_f16(o[jn], pl[2 * kp2],     vh4[0], vh4[1]);
                mma_f16(o[jn], ph[2 * kp2 + 1], vh4[2], vh4[3]);
                mma_f16(o[jn], ph[2 * kp2 + 1], vl4[2], vl4[3]);
                mma_f16(o[jn], pl[2 * kp2 + 1], vh4[2], vh4[3]);
            }
        }

        __syncthreads();
        if (kt + 2 < 32) load_kv(kt + 2, kt & 1);
        CP_COMMIT();
        if (kt + 1 < 32) {
            CP_WAIT1();
            __syncthreads();
        }
    }

    float inv0 = 1.0f / l0, inv1 = 1.0f / l1;
    const size_t row0 = (tok0 + qt * 128 + wid * 16 + gr) * 1024 + h * 64;
    const size_t row1 = row0 + 8 * 1024;
#pragma unroll
    for (int jn = 0; jn < 8; jn++) {
        int cc = jn * 8 + 2 * qq;
        uint32_t hi, lo;
        split2h(o[jn][0] * inv0, o[jn][1] * inv0, hi, lo);
        *(uint32_t*)&oh[row0 + cc] = hi;
        *(uint32_t*)&ol[row0 + cc] = lo;
        split2h(o[jn][2] * inv1, o[jn][3] * inv1, hi, lo);
        *(uint32_t*)&oh[row1 + cc] = hi;
        *(uint32_t*)&ol[row1 + cc] = lo;
    }
}

// ---------------------------------------------------------------------------
// Launch: fused split -> QKV GEMM (split out) -> flash (split out) -> out GEMM
// ---------------------------------------------------------------------------
extern "C" void kernel_launch(void* const* d_in, const int* in_sizes, int n_in,
                              void* d_out, int out_size) {
    const float* x     = (const float*)d_in[0];  // [2,2048,1024]
    const float* w_qkv = (const float*)d_in[1];  // [3072,1024]
    const float* w_out = (const float*)d_in[2];  // [1024,1024]
    float* out = (float*)d_out;                  // [2,2048,1024]

    __half *xh, *xl, *wq, *wo, *qh, *ql, *ah, *al;
    cudaGetSymbolAddress((void**)&xh, g_xh);  cudaGetSymbolAddress((void**)&xl, g_xl);
    cudaGetSymbolAddress((void**)&wq, g_wq);  cudaGetSymbolAddress((void**)&wo, g_wo);
    cudaGetSymbolAddress((void**)&qh, g_qh);  cudaGetSymbolAddress((void**)&ql, g_ql);
    cudaGetSymbolAddress((void**)&ah, g_ah);  cudaGetSymbolAddress((void**)&al, g_al);

    cudaFuncSetAttribute(flash_attn, cudaFuncAttributeMaxDynamicSharedMemorySize, FLASH_SMEM);
    cudaFuncSetAttribute(gemm_mma<true>, cudaFuncAttributeMaxDynamicSharedMemorySize, GEMM_SMEM);
    cudaFuncSetAttribute(gemm_mma<false>, cudaFuncAttributeMaxDynamicSharedMemorySize, GEMM_SMEM);

    dim3 blk(256);
    split_all<<<(X4 + W4 + O4) / 256, blk>>>(x, w_qkv, w_out, xh, xl, wq, wo);
    // QKV: [4096,3072] = (xh+xl) @ wq^T  -> fp16 hi/lo
    gemm_mma<true><<<dim3(3072 / 128, 4096 / 128), blk, GEMM_SMEM>>>(
        xh, xl, wq, nullptr, qh, ql, 1024, 3072);
    // Attention -> fp16 hi/lo
    flash_attn<<<dim3(16, 32), blk, FLASH_SMEM>>>(qh, ql, ah, al);
    // Out: [4096,1024] = (ah+al) @ wo^T -> fp32
    gemm_mma<false><<<dim3(1024 / 128, 4096 / 128), blk, GEMM_SMEM>>>(
        ah, al, wo, out, nullptr, nullptr, 1024, 1024);
}

// round 14
// speedup vs baseline: 1.4015x; 1.1183x over previous
#include <cuda_runtime.h>
#include <cuda_fp16.h>
#include <math.h>
#include <stdint.h>

// ---------------------------------------------------------------------------
// Scratch (allocation-free rule: device globals)  — all fp16
// ---------------------------------------------------------------------------
__device__ __half g_xh[4096 * 1024],  g_xl[4096 * 1024];   // x hi/lo
__device__ __half g_wq[3072 * 1024];                       // w_qkv single fp16
__device__ __half g_wo[1024 * 1024];                       // w_out single fp16
__device__ __half g_qh[4096 * 3072],  g_ql[4096 * 3072];   // qkv hi/lo
__device__ __half g_ah[4096 * 1024],  g_al[4096 * 1024];   // attn hi/lo

// ---------------------------------------------------------------------------
// Helpers
// ---------------------------------------------------------------------------
__device__ __forceinline__ uint32_t smem_u32(const void* p) {
    uint32_t a;
    asm("{ .reg .u64 t; cvta.to.shared.u64 t, %1; cvt.u32.u64 %0, t; }" : "=r"(a) : "l"(p));
    return a;
}
__device__ __forceinline__ float ex2(float x) {
    float r; asm("ex2.approx.f32 %0, %1;" : "=f"(r) : "f"(x)); return r;
}
__device__ __forceinline__ uint32_t packh(float x, float y) {
    uint32_t h;
    asm("cvt.rn.f16x2.f32 %0, %1, %2;" : "=r"(h) : "f"(y), "f"(x));
    return h;
}
__device__ __forceinline__ void split2h(float x, float y, uint32_t& hi, uint32_t& lo) {
    uint32_t h = packh(x, y);
    __half2 h2 = *(__half2*)&h;
    float2 f = __half22float2(h2);
    hi = h;
    lo = packh(x - f.x, y - f.y);
}
__device__ __forceinline__ void split4h(float4 v, uint2& hi, uint2& lo) {
    split2h(v.x, v.y, hi.x, lo.x);
    split2h(v.z, v.w, hi.y, lo.y);
}
__device__ __forceinline__ void mma_f16(float c[4], const uint32_t a[4],
                                        uint32_t b0, uint32_t b1) {
    asm volatile(
        "mma.sync.aligned.m16n8k16.row.col.f32.f16.f16.f32 "
        "{%0,%1,%2,%3}, {%4,%5,%6,%7}, {%8,%9}, {%0,%1,%2,%3};"
        : "+f"(c[0]), "+f"(c[1]), "+f"(c[2]), "+f"(c[3])
        : "r"(a[0]), "r"(a[1]), "r"(a[2]), "r"(a[3]), "r"(b0), "r"(b1));
}
__device__ __forceinline__ void ldm_x4(uint32_t r[4], uint32_t addr) {
    asm volatile("ldmatrix.sync.aligned.m8n8.x4.shared.b16 {%0,%1,%2,%3}, [%4];"
                 : "=r"(r[0]), "=r"(r[1]), "=r"(r[2]), "=r"(r[3]) : "r"(addr));
}
__device__ __forceinline__ void ldm_x4_trans(uint32_t r[4], uint32_t addr) {
    asm volatile("ldmatrix.sync.aligned.m8n8.x4.trans.shared.b16 {%0,%1,%2,%3}, [%4];"
                 : "=r"(r[0]), "=r"(r[1]), "=r"(r[2]), "=r"(r[3]) : "r"(addr));
}
__device__ __forceinline__ void cp16(uint32_t saddr, const void* g) {
    asm volatile("cp.async.cg.shared.global [%0], [%1], 16;" :: "r"(saddr), "l"(g));
}
#define CP_COMMIT() asm volatile("cp.async.commit_group;" ::: "memory")
#define CP_WAIT1()  asm volatile("cp.async.wait_group 1;" ::: "memory")

// ---------------------------------------------------------------------------
// fused split kernel: x -> fp16 hi/lo;  w_qkv, w_out -> single fp16
// ---------------------------------------------------------------------------
#define X4 (4096 * 1024 / 4)
#define W4 (3072 * 1024 / 4)
#define O4 (1024 * 1024 / 4)

__global__ void split_all(const float* __restrict__ x,
                          const float* __restrict__ wq,
                          const float* __restrict__ wo,
                          __half* __restrict__ xh, __half* __restrict__ xl,
                          __half* __restrict__ wqh, __half* __restrict__ woh) {
    int i = blockIdx.x * blockDim.x + threadIdx.x;
    if (i < X4) {
        float4 v = ((const float4*)x)[i];
        uint2 h, l;
        split4h(v, h, l);
        ((uint2*)xh)[i] = h; ((uint2*)xl)[i] = l;
    } else if (i < X4 + W4) {
        int j = i - X4;
        float4 v = ((const float4*)wq)[j];
        uint2 h;
        h.x = packh(v.x, v.y); h.y = packh(v.z, v.w);
        ((uint2*)wqh)[j] = h;
    } else {
        int j = i - X4 - W4;
        float4 v = ((const float4*)wo)[j];
        uint2 h;
        h.x = packh(v.x, v.y); h.y = packh(v.z, v.w);
        ((uint2*)woh)[j] = h;
    }
}

// ---------------------------------------------------------------------------
// fp16 asymmetric 2-term GEMM:  C = (Ah + Al) @ B^T,  B single fp16.
// (unchanged from R13)
// ---------------------------------------------------------------------------
#define ARR_B  8192
#define STG_B  (3 * ARR_B)
#define NSTG   3
#define GEMM_SMEM (NSTG * STG_B)     // 73728 -> 2 CTAs/SM

template <bool SPLITC>
__global__ __launch_bounds__(256, 2) void gemm_mma(const __half* __restrict__ Ahg,
                                                   const __half* __restrict__ Alg,
                                                   const __half* __restrict__ Bg,
                                                   float* __restrict__ C,
                                                   __half* __restrict__ Ch,
                                                   __half* __restrict__ Cl,
                                                   int K, int N) {
    extern __shared__ __align__(16) char gsm[];
    const uint32_t sbase = smem_u32(gsm);

    const int tid = threadIdx.x;
    const int wid = tid >> 5;
    const int lane = tid & 31;
    const int wr = wid >> 2;
    const int wc = wid & 3;
    const int gr = lane >> 2, qq = lane & 3;
    const int row0 = blockIdx.y * 128;
    const int col0 = blockIdx.x * 128;
    const int NCH = K >> 5;

    auto load_chunk = [&](int kc, int stg) {
        const uint32_t st = sbase + stg * STG_B;
#pragma unroll
        for (int t = 0; t < 6; t++) {
            int idx = tid + t * 256;
            int arr = idx >> 9;
            int rem = idx & 511;
            int row = rem >> 2;
            int ch = rem & 3;
            uint32_t sa = st + arr * ARR_B + row * 64 + ((ch ^ ((row >> 1) & 3)) << 4);
            const __half* gp;
            int kcol = kc * 32 + ch * 8;
            if (arr == 0)      gp = &Ahg[(size_t)(row0 + row) * K + kcol];
            else if (arr == 1) gp = &Alg[(size_t)(row0 + row) * K + kcol];
            else               gp = &Bg[(size_t)(col0 + row) * K + kcol];
            cp16(sa, gp);
        }
    };

    float acc[4][4][4] = {};

    load_chunk(0, 0);
    CP_COMMIT();
    load_chunk(1, 1);
    CP_COMMIT();

    const uint32_t lrow = lane & 15;
    const int kbase = lane >> 4;
    const uint32_t sw = (lrow >> 1) & 3;
    uint32_t aoff[4], boff[2];
#pragma unroll
    for (int i = 0; i < 4; i++) aoff[i] = (wr * 64 + i * 16 + lrow) * 64;
#pragma unroll
    for (int g = 0; g < 2; g++) boff[g] = (wc * 32 + g * 16 + lrow) * 64;

    for (int c = 0; c < NCH; c++) {
        CP_WAIT1();
        __syncthreads();
        int nc = c + 2;
        if (nc < NCH) load_chunk(nc, nc % 3);
        CP_COMMIT();

        const uint32_t st = sbase + (c % 3) * STG_B;
        const uint32_t ah = st, al = st + ARR_B, bh = st + 2 * ARR_B;
#pragma unroll
        for (int ks = 0; ks < 2; ks++) {
            const uint32_t scol = (uint32_t)(((ks * 2 + kbase) ^ sw) << 4);
            uint32_t fa[4][4], fb[4][2];
#pragma unroll
            for (int i = 0; i < 4; i++)
                ldm_x4(fa[i], ah + aoff[i] + scol);
#pragma unroll
            for (int g = 0; g < 2; g++) {
                uint32_t r[4];
                ldm_x4(r, bh + boff[g] + scol);
                fb[2 * g][0] = r[0]; fb[2 * g][1] = r[2];
                fb[2 * g + 1][0] = r[1]; fb[2 * g + 1][1] = r[3];
            }
#pragma unroll
            for (int i = 0; i < 4; i++)
#pragma unroll
                for (int j = 0; j < 4; j++)
                    mma_f16(acc[i][j], fa[i], fb[j][0], fb[j][1]);
#pragma unroll
            for (int i = 0; i < 4; i++)
                ldm_x4(fa[i], al + aoff[i] + scol);
#pragma unroll
            for (int i = 0; i < 4; i++)
#pragma unroll
                for (int j = 0; j < 4; j++)
                    mma_f16(acc[i][j], fa[i], fb[j][0], fb[j][1]);
        }
    }

#pragma unroll
    for (int i = 0; i < 4; i++) {
        int r0g = row0 + wr * 64 + i * 16 + gr;
#pragma unroll
        for (int j = 0; j < 4; j++) {
            int cg = col0 + wc * 32 + j * 8 + 2 * qq;
            if (SPLITC) {
                uint32_t hi, lo;
                split2h(acc[i][j][0], acc[i][j][1], hi, lo);
                *(uint32_t*)&Ch[(size_t)r0g * N + cg] = hi;
                *(uint32_t*)&Cl[(size_t)r0g * N + cg] = lo;
                split2h(acc[i][j][2], acc[i][j][3], hi, lo);
                *(uint32_t*)&Ch[(size_t)(r0g + 8) * N + cg] = hi;
                *(uint32_t*)&Cl[(size_t)(r0g + 8) * N + cg] = lo;
            } else {
                *(float2*)&C[(size_t)r0g * N + cg] = make_float2(acc[i][j][0], acc[i][j][1]);
                *(float2*)&C[(size_t)(r0g + 8) * N + cg] = make_float2(acc[i][j][2], acc[i][j][3]);
            }
        }
    }
}

// ---------------------------------------------------------------------------
// Flash attention: QK 3-term (fp16 hi/lo both sides), PV 2-term (V single fp16).
// cp.async double-buffer; KV stage = {Kh, Kl, V}. 128 q-rows x (b,h), 8 warps.
// ---------------------------------------------------------------------------
#define FP     72                       // fp16 row pitch (144 B)
#define FQ_B   (128 * FP * 2)           // Q array bytes (18432)
#define KV_B   (64 * FP * 2)            // per-array bytes (9216)
#define KVS_B  (3 * KV_B)               // KV stage: Kh Kl V = 27648
#define FLASH_SMEM (2 * FQ_B + 2 * KVS_B)   // 92160

__global__ __launch_bounds__(256, 2) void flash_attn(const __half* __restrict__ qh,
                                                     const __half* __restrict__ ql,
                                                     __half* __restrict__ oh,
                                                     __half* __restrict__ ol) {
    extern __shared__ __align__(16) char fsmc[];
    const uint32_t sb = smem_u32(fsmc);
    __half* Qh = (__half*)fsmc;

    const int tid = threadIdx.x;
    const int wid = tid >> 5;
    const int lane = tid & 31;
    const int gr = lane >> 2;
    const int qq = lane & 3;

    const int qt = blockIdx.x;
    const int b  = blockIdx.y >> 4;
    const int h  = blockIdx.y & 15;

    const size_t tok0 = (size_t)b * 2048;
    const int qoff = h * 64, koff = 1024 + h * 64, voff = 2048 + h * 64;
    const float QS = 0.125f * 1.4426950408889634f;   // 1/sqrt(64) * log2(e)

    // ---- async load Q (2 arrays x 128 rows x 8 chunks) ----
#pragma unroll
    for (int i = 0; i < 8; i++) {
        int idx = tid + i * 256;
        int arr = idx >> 10;
        int rem = idx & 1023;
        int row = rem >> 3, ch = rem & 7;
        const __half* src = (arr ? ql : qh) +
            (tok0 + qt * 128 + row) * 3072 + qoff + ch * 8;
        cp16(sb + arr * FQ_B + row * 144 + ch * 16, src);
    }
    // KV loader: 3 arrays (Kh, Kl, V) x 64 rows x 8 chunks = 1536 -> 6/thread
    auto load_kv = [&](int kt, int s) {
        const uint32_t st = sb + 2 * FQ_B + s * KVS_B;
#pragma unroll
        for (int i = 0; i < 6; i++) {
            int idx = tid + i * 256;
            int arr = idx >> 9;
            int rem = idx & 511;
            int row = rem >> 3, ch = rem & 7;
            const __half* src;
            if (arr == 0)      src = qh + (tok0 + kt * 64 + row) * 3072 + koff + ch * 8;
            else if (arr == 1) src = ql + (tok0 + kt * 64 + row) * 3072 + koff + ch * 8;
            else               src = qh + (tok0 + kt * 64 + row) * 3072 + voff + ch * 8;
            cp16(st + arr * KV_B + row * 144 + ch * 16, src);
        }
    };

    load_kv(0, 0);
    CP_COMMIT();
    load_kv(1, 1);
    CP_COMMIT();
    CP_WAIT1();
    __syncthreads();

    uint32_t qa_h[4][4];
    const int qrow = wid * 16;
    const uint32_t ql_u = sb + FQ_B;
    const uint32_t lrow16 = lane & 15;
    const uint32_t lcol8 = (lane >> 4) << 3;
    const uint32_t qfrag_off = (qrow + lrow16) * 144 + lcol8 * 2;
#pragma unroll
    for (int kap = 0; kap < 4; kap++) {
        int cb = kap * 16 + 2 * qq;
        qa_h[kap][0] = *(const uint32_t*)&Qh[(qrow + gr) * FP + cb];
        qa_h[kap][1] = *(const uint32_t*)&Qh[(qrow + gr + 8) * FP + cb];
        qa_h[kap][2] = *(const uint32_t*)&Qh[(qrow + gr) * FP + cb + 8];
        qa_h[kap][3] = *(const uint32_t*)&Qh[(qrow + gr + 8) * FP + cb + 8];
    }

    float m0 = -1e30f, m1 = -1e30f, l0 = 0.0f, l1 = 0.0f;
    float o[8][4] = {};

    for (int kt = 0; kt < 32; kt++) {
        const uint32_t st = sb + 2 * FQ_B + (kt & 1) * KVS_B;
        const uint32_t kh_u = st;
        const uint32_t kl_u = st + KV_B;
        const uint32_t vh_u = st + 2 * KV_B;

        // ---- S = Q @ K^T (3-term) ----
        float S[8][4];
#pragma unroll
        for (int j = 0; j < 8; j++) { S[j][0] = S[j][1] = S[j][2] = S[j][3] = 0.0f; }
#pragma unroll
        for (int kap = 0; kap < 4; kap++) {
            uint32_t qa_l[4];
            ldm_x4(qa_l, ql_u + qfrag_off + kap * 32);
            const uint32_t koff2 = (kap * 16 + lcol8) * 2;
#pragma unroll
            for (int jp = 0; jp < 4; jp++) {
                uint32_t rh[4], rl[4];
                const uint32_t rowa = (jp * 16 + lrow16) * 144 + koff2;
                ldm_x4(rh, kh_u + rowa);
                ldm_x4(rl, kl_u + rowa);
                mma_f16(S[2 * jp],     qa_h[kap], rh[0], rh[2]);
                mma_f16(S[2 * jp + 1], qa_h[kap], rh[1], rh[3]);
                mma_f16(S[2 * jp],     qa_h[kap], rl[0], rl[2]);
                mma_f16(S[2 * jp + 1], qa_h[kap], rl[1], rl[3]);
                mma_f16(S[2 * jp],     qa_l, rh[0], rh[2]);
                mma_f16(S[2 * jp + 1], qa_l, rh[1], rh[3]);
            }
        }
#pragma unroll
        for (int j = 0; j < 8; j++) {
            S[j][0] *= QS; S[j][1] *= QS; S[j][2] *= QS; S[j][3] *= QS;
        }

        // ---- online softmax ----
        float t0 = -1e30f, t1 = -1e30f;
#pragma unroll
        for (int j = 0; j < 8; j++) {
            t0 = fmaxf(t0, fmaxf(S[j][0], S[j][1]));
            t1 = fmaxf(t1, fmaxf(S[j][2], S[j][3]));
        }
        t0 = fmaxf(t0, __shfl_xor_sync(0xffffffffu, t0, 1));
        t0 = fmaxf(t0, __shfl_xor_sync(0xffffffffu, t0, 2));
        t1 = fmaxf(t1, __shfl_xor_sync(0xffffffffu, t1, 1));
        t1 = fmaxf(t1, __shfl_xor_sync(0xffffffffu, t1, 2));
        float mn0 = fmaxf(m0, t0), mn1 = fmaxf(m1, t1);
        float al0 = ex2(m0 - mn0), al1 = ex2(m1 - mn1);
        m0 = mn0; m1 = mn1;

        float rs0 = 0.0f, rs1 = 0.0f;
#pragma unroll
        for (int j = 0; j < 8; j++) {
            S[j][0] = ex2(S[j][0] - m0);
            S[j][1] = ex2(S[j][1] - m0);
            S[j][2] = ex2(S[j][2] - m1);
            S[j][3] = ex2(S[j][3] - m1);
            rs0 += S[j][0] + S[j][1];
            rs1 += S[j][2] + S[j][3];
        }
        rs0 += __shfl_xor_sync(0xffffffffu, rs0, 1);
        rs0 += __shfl_xor_sync(0xffffffffu, rs0, 2);
        rs1 += __shfl_xor_sync(0xffffffffu, rs1, 1);
        rs1 += __shfl_xor_sync(0xffffffffu, rs1, 2);
        l0 = l0 * al0 + rs0;
        l1 = l1 * al1 + rs1;
#pragma unroll
        for (int jn = 0; jn < 8; jn++) {
            o[jn][0] *= al0; o[jn][1] *= al0;
            o[jn][2] *= al1; o[jn][3] *= al1;
        }

        // ---- split P into fp16 hi/lo A-fragments ----
        uint32_t ph[4][4], pl[4][4];
#pragma unroll
        for (int kap = 0; kap < 4; kap++) {
            const float* s0 = S[2 * kap];
            const float* s1 = S[2 * kap + 1];
            split2h(s0[0], s0[1], ph[kap][0], pl[kap][0]);
            split2h(s0[2], s0[3], ph[kap][1], pl[kap][1]);
            split2h(s1[0], s1[1], ph[kap][2], pl[kap][2]);
            split2h(s1[2], s1[3], ph[kap][3], pl[kap][3]);
        }

        // ---- O += P @ V  (2-term: Ph·V + Pl·V, V single fp16) ----
#pragma unroll
        for (int jn = 0; jn < 8; jn++) {
#pragma unroll
            for (int kp2 = 0; kp2 < 2; kp2++) {
                uint32_t vh4[4];
                ldm_x4_trans(vh4, vh_u + (kp2 * 32 + lane) * 144 + jn * 16);
                mma_f16(o[jn], ph[2 * kp2],     vh4[0], vh4[1]);
                mma_f16(o[jn], pl[2 * kp2],     vh4[0], vh4[1]);
                mma_f16(o[jn], ph[2 * kp2 + 1], vh4[2], vh4[3]);
                mma_f16(o[jn], pl[2 * kp2 + 1], vh4[2], vh4[3]);
            }
        }

        // ---- prefetch KV(kt+2) ----
        __syncthreads();
        if (kt + 2 < 32) load_kv(kt + 2, kt & 1);
        CP_COMMIT();
        if (kt + 1 < 32) {
            CP_WAIT1();
            __syncthreads();
        }
    }

    // ---- epilogue: normalize, split, store fp16 hi/lo (b, s, h*64+d) ----
    float inv0 = 1.0f / l0, inv1 = 1.0f / l1;
    const size_t row0 = (tok0 + qt * 128 + wid * 16 + gr) * 1024 + h * 64;
    const size_t row1 = row0 + 8 * 1024;
#pragma unroll
    for (int jn = 0; jn < 8; jn++) {
        int cc = jn * 8 + 2 * qq;
        uint32_t hi, lo;
        split2h(o[jn][0] * inv0, o[jn][1] * inv0, hi, lo);
        *(uint32_t*)&oh[row0 + cc] = hi;
        *(uint32_t*)&ol[row0 + cc] = lo;
        split2h(o[jn][2] * inv1, o[jn][3] * inv1, hi, lo);
        *(uint32_t*)&oh[row1 + cc] = hi;
        *(uint32_t*)&ol[row1 + cc] = lo;
    }
}

// ---------------------------------------------------------------------------
// Launch
// ---------------------------------------------------------------------------
extern "C" void kernel_launch(void* const* d_in, const int* in_sizes, int n_in,
                              void* d_out, int out_size) {
    const float* x     = (const float*)d_in[0];  // [2,2048,1024]
    const float* w_qkv = (const float*)d_in[1];  // [3072,1024]
    const float* w_out = (const float*)d_in[2];  // [1024,1024]
    float* out = (float*)d_out;                  // [2,2048,1024]

    __half *xh, *xl, *wq, *wo, *qh, *ql, *ah, *al;
    cudaGetSymbolAddress((void**)&xh, g_xh);  cudaGetSymbolAddress((void**)&xl, g_xl);
    cudaGetSymbolAddress((void**)&wq, g_wq);  cudaGetSymbolAddress((void**)&wo, g_wo);
    cudaGetSymbolAddress((void**)&qh, g_qh);  cudaGetSymbolAddress((void**)&ql, g_ql);
    cudaGetSymbolAddress((void**)&ah, g_ah);  cudaGetSymbolAddress((void**)&al, g_al);

    cudaFuncSetAttribute(flash_attn, cudaFuncAttributeMaxDynamicSharedMemorySize, FLASH_SMEM);
    cudaFuncSetAttribute(gemm_mma<true>, cudaFuncAttributeMaxDynamicSharedMemorySize, GEMM_SMEM);
    cudaFuncSetAttribute(gemm_mma<false>, cudaFuncAttributeMaxDynamicSharedMemorySize, GEMM_SMEM);

    dim3 blk(256);
    split_all<<<(X4 + W4 + O4) / 256, blk>>>(x, w_qkv, w_out, xh, xl, wq, wo);
    // QKV: [4096,3072] = (xh+xl) @ wq^T  -> fp16 hi/lo
    gemm_mma<true><<<dim3(3072 / 128, 4096 / 128), blk, GEMM_SMEM>>>(
        xh, xl, wq, nullptr, qh, ql, 1024, 3072);
    // Attention -> fp16 hi/lo
    flash_attn<<<dim3(16, 32), blk, FLASH_SMEM>>>(qh, ql, ah, al);
    // Out: [4096,1024] = (ah+al) @ wo^T -> fp32
    gemm_mma<false><<<dim3(1024 / 128, 4096 / 128), blk, GEMM_SMEM>>>(
        ah, al, wo, out, nullptr, nullptr, 1024, 1024);
}

// round 15
// speedup vs baseline: 1.5397x; 1.0986x over previous
#include <cuda_runtime.h>
#include <cuda_fp16.h>
#include <math.h>
#include <stdint.h>

// ---------------------------------------------------------------------------
// Scratch (allocation-free rule: device globals)  — all fp16
// ---------------------------------------------------------------------------
__device__ __half g_xh[4096 * 1024],  g_xl[4096 * 1024];   // x hi/lo
__device__ __half g_wq[3072 * 1024];                       // w_qkv single fp16
__device__ __half g_wo[1024 * 1024];                       // w_out single fp16
__device__ __half g_qh[4096 * 3072],  g_ql[4096 * 3072];   // qkv hi/lo
__device__ __half g_ah[4096 * 1024],  g_al[4096 * 1024];   // attn hi/lo

// ---------------------------------------------------------------------------
// Helpers
// ---------------------------------------------------------------------------
__device__ __forceinline__ uint32_t smem_u32(const void* p) {
    uint32_t a;
    asm("{ .reg .u64 t; cvta.to.shared.u64 t, %1; cvt.u32.u64 %0, t; }" : "=r"(a) : "l"(p));
    return a;
}
__device__ __forceinline__ float ex2(float x) {
    float r; asm("ex2.approx.f32 %0, %1;" : "=f"(r) : "f"(x)); return r;
}
__device__ __forceinline__ uint32_t packh(float x, float y) {
    uint32_t h;
    asm("cvt.rn.f16x2.f32 %0, %1, %2;" : "=r"(h) : "f"(y), "f"(x));
    return h;
}
__device__ __forceinline__ void split2h(float x, float y, uint32_t& hi, uint32_t& lo) {
    uint32_t h = packh(x, y);
    __half2 h2 = *(__half2*)&h;
    float2 f = __half22float2(h2);
    hi = h;
    lo = packh(x - f.x, y - f.y);
}
__device__ __forceinline__ void split4h(float4 v, uint2& hi, uint2& lo) {
    split2h(v.x, v.y, hi.x, lo.x);
    split2h(v.z, v.w, hi.y, lo.y);
}
__device__ __forceinline__ void mma_f16(float c[4], const uint32_t a[4],
                                        uint32_t b0, uint32_t b1) {
    asm volatile(
        "mma.sync.aligned.m16n8k16.row.col.f32.f16.f16.f32 "
        "{%0,%1,%2,%3}, {%4,%5,%6,%7}, {%8,%9}, {%0,%1,%2,%3};"
        : "+f"(c[0]), "+f"(c[1]), "+f"(c[2]), "+f"(c[3])
        : "r"(a[0]), "r"(a[1]), "r"(a[2]), "r"(a[3]), "r"(b0), "r"(b1));
}
__device__ __forceinline__ void ldm_x4(uint32_t r[4], uint32_t addr) {
    asm volatile("ldmatrix.sync.aligned.m8n8.x4.shared.b16 {%0,%1,%2,%3}, [%4];"
                 : "=r"(r[0]), "=r"(r[1]), "=r"(r[2]), "=r"(r[3]) : "r"(addr));
}
__device__ __forceinline__ void ldm_x4_trans(uint32_t r[4], uint32_t addr) {
    asm volatile("ldmatrix.sync.aligned.m8n8.x4.trans.shared.b16 {%0,%1,%2,%3}, [%4];"
                 : "=r"(r[0]), "=r"(r[1]), "=r"(r[2]), "=r"(r[3]) : "r"(addr));
}
__device__ __forceinline__ void cp16(uint32_t saddr, const void* g) {
    asm volatile("cp.async.cg.shared.global [%0], [%1], 16;" :: "r"(saddr), "l"(g));
}
#define CP_COMMIT() asm volatile("cp.async.commit_group;" ::: "memory")
#define CP_WAIT1()  asm volatile("cp.async.wait_group 1;" ::: "memory")

// ---------------------------------------------------------------------------
// fused split kernel: x -> fp16 hi/lo;  w_qkv, w_out -> single fp16
// ---------------------------------------------------------------------------
#define X4 (4096 * 1024 / 4)
#define W4 (3072 * 1024 / 4)
#define O4 (1024 * 1024 / 4)

__global__ void split_all(const float* __restrict__ x,
                          const float* __restrict__ wq,
                          const float* __restrict__ wo,
                          __half* __restrict__ xh, __half* __restrict__ xl,
                          __half* __restrict__ wqh, __half* __restrict__ woh) {
    int i = blockIdx.x * blockDim.x + threadIdx.x;
    if (i < X4) {
        float4 v = ((const float4*)x)[i];
        uint2 h, l;
        split4h(v, h, l);
        ((uint2*)xh)[i] = h; ((uint2*)xl)[i] = l;
    } else if (i < X4 + W4) {
        int j = i - X4;
        float4 v = ((const float4*)wq)[j];
        uint2 h;
        h.x = packh(v.x, v.y); h.y = packh(v.z, v.w);
        ((uint2*)wqh)[j] = h;
    } else {
        int j = i - X4 - W4;
        float4 v = ((const float4*)wo)[j];
        uint2 h;
        h.x = packh(v.x, v.y); h.y = packh(v.z, v.w);
        ((uint2*)woh)[j] = h;
    }
}

// ---------------------------------------------------------------------------
// fp16 asymmetric 2-term GEMM:  C = (Ah + Al) @ B^T,  B single fp16.
// (unchanged from R13/R14)
// ---------------------------------------------------------------------------
#define ARR_B  8192
#define STG_B  (3 * ARR_B)
#define NSTG   3
#define GEMM_SMEM (NSTG * STG_B)     // 73728 -> 2 CTAs/SM

template <bool SPLITC>
__global__ __launch_bounds__(256, 2) void gemm_mma(const __half* __restrict__ Ahg,
                                                   const __half* __restrict__ Alg,
                                                   const __half* __restrict__ Bg,
                                                   float* __restrict__ C,
                                                   __half* __restrict__ Ch,
                                                   __half* __restrict__ Cl,
                                                   int K, int N) {
    extern __shared__ __align__(16) char gsm[];
    const uint32_t sbase = smem_u32(gsm);

    const int tid = threadIdx.x;
    const int wid = tid >> 5;
    const int lane = tid & 31;
    const int wr = wid >> 2;
    const int wc = wid & 3;
    const int gr = lane >> 2, qq = lane & 3;
    const int row0 = blockIdx.y * 128;
    const int col0 = blockIdx.x * 128;
    const int NCH = K >> 5;

    auto load_chunk = [&](int kc, int stg) {
        const uint32_t st = sbase + stg * STG_B;
#pragma unroll
        for (int t = 0; t < 6; t++) {
            int idx = tid + t * 256;
            int arr = idx >> 9;
            int rem = idx & 511;
            int row = rem >> 2;
            int ch = rem & 3;
            uint32_t sa = st + arr * ARR_B + row * 64 + ((ch ^ ((row >> 1) & 3)) << 4);
            const __half* gp;
            int kcol = kc * 32 + ch * 8;
            if (arr == 0)      gp = &Ahg[(size_t)(row0 + row) * K + kcol];
            else if (arr == 1) gp = &Alg[(size_t)(row0 + row) * K + kcol];
            else               gp = &Bg[(size_t)(col0 + row) * K + kcol];
            cp16(sa, gp);
        }
    };

    float acc[4][4][4] = {};

    load_chunk(0, 0);
    CP_COMMIT();
    load_chunk(1, 1);
    CP_COMMIT();

    const uint32_t lrow = lane & 15;
    const int kbase = lane >> 4;
    const uint32_t sw = (lrow >> 1) & 3;
    uint32_t aoff[4], boff[2];
#pragma unroll
    for (int i = 0; i < 4; i++) aoff[i] = (wr * 64 + i * 16 + lrow) * 64;
#pragma unroll
    for (int g = 0; g < 2; g++) boff[g] = (wc * 32 + g * 16 + lrow) * 64;

    for (int c = 0; c < NCH; c++) {
        CP_WAIT1();
        __syncthreads();
        int nc = c + 2;
        if (nc < NCH) load_chunk(nc, nc % 3);
        CP_COMMIT();

        const uint32_t st = sbase + (c % 3) * STG_B;
        const uint32_t ah = st, al = st + ARR_B, bh = st + 2 * ARR_B;
#pragma unroll
        for (int ks = 0; ks < 2; ks++) {
            const uint32_t scol = (uint32_t)(((ks * 2 + kbase) ^ sw) << 4);
            uint32_t fa[4][4], fb[4][2];
#pragma unroll
            for (int i = 0; i < 4; i++)
                ldm_x4(fa[i], ah + aoff[i] + scol);
#pragma unroll
            for (int g = 0; g < 2; g++) {
                uint32_t r[4];
                ldm_x4(r, bh + boff[g] + scol);
                fb[2 * g][0] = r[0]; fb[2 * g][1] = r[2];
                fb[2 * g + 1][0] = r[1]; fb[2 * g + 1][1] = r[3];
            }
#pragma unroll
            for (int i = 0; i < 4; i++)
#pragma unroll
                for (int j = 0; j < 4; j++)
                    mma_f16(acc[i][j], fa[i], fb[j][0], fb[j][1]);
#pragma unroll
            for (int i = 0; i < 4; i++)
                ldm_x4(fa[i], al + aoff[i] + scol);
#pragma unroll
            for (int i = 0; i < 4; i++)
#pragma unroll
                for (int j = 0; j < 4; j++)
                    mma_f16(acc[i][j], fa[i], fb[j][0], fb[j][1]);
        }
    }

#pragma unroll
    for (int i = 0; i < 4; i++) {
        int r0g = row0 + wr * 64 + i * 16 + gr;
#pragma unroll
        for (int j = 0; j < 4; j++) {
            int cg = col0 + wc * 32 + j * 8 + 2 * qq;
            if (SPLITC) {
                uint32_t hi, lo;
                split2h(acc[i][j][0], acc[i][j][1], hi, lo);
                *(uint32_t*)&Ch[(size_t)r0g * N + cg] = hi;
                *(uint32_t*)&Cl[(size_t)r0g * N + cg] = lo;
                split2h(acc[i][j][2], acc[i][j][3], hi, lo);
                *(uint32_t*)&Ch[(size_t)(r0g + 8) * N + cg] = hi;
                *(uint32_t*)&Cl[(size_t)(r0g + 8) * N + cg] = lo;
            } else {
                *(float2*)&C[(size_t)r0g * N + cg] = make_float2(acc[i][j][0], acc[i][j][1]);
                *(float2*)&C[(size_t)(r0g + 8) * N + cg] = make_float2(acc[i][j][2], acc[i][j][3]);
            }
        }
    }
}

// ---------------------------------------------------------------------------
// Flash attention: QK 2-term (Q hi/lo, K single), PV 2-term (P hi/lo, V single).
// cp.async double-buffer; KV stage = {K, V}. 128 q-rows x (b,h), 8 warps.
// ---------------------------------------------------------------------------
#define FP     72                       // fp16 row pitch (144 B)
#define FQ_B   (128 * FP * 2)           // Q array bytes (18432)
#define KV_B   (64 * FP * 2)            // per-array bytes (9216)
#define KVS_B  (2 * KV_B)               // KV stage: K V = 18432
#define FLASH_SMEM (2 * FQ_B + 2 * KVS_B)   // 73728

__global__ __launch_bounds__(256, 2) void flash_attn(const __half* __restrict__ qh,
                                                     const __half* __restrict__ ql,
                                                     __half* __restrict__ oh,
                                                     __half* __restrict__ ol) {
    extern __shared__ __align__(16) char fsmc[];
    const uint32_t sb = smem_u32(fsmc);
    __half* Qh = (__half*)fsmc;

    const int tid = threadIdx.x;
    const int wid = tid >> 5;
    const int lane = tid & 31;
    const int gr = lane >> 2;
    const int qq = lane & 3;

    const int qt = blockIdx.x;
    const int b  = blockIdx.y >> 4;
    const int h  = blockIdx.y & 15;

    const size_t tok0 = (size_t)b * 2048;
    const int qoff = h * 64, koff = 1024 + h * 64, voff = 2048 + h * 64;
    const float QS = 0.125f * 1.4426950408889634f;   // 1/sqrt(64) * log2(e)

    // ---- async load Q (2 arrays x 128 rows x 8 chunks) ----
#pragma unroll
    for (int i = 0; i < 8; i++) {
        int idx = tid + i * 256;
        int arr = idx >> 10;
        int rem = idx & 1023;
        int row = rem >> 3, ch = rem & 7;
        const __half* src = (arr ? ql : qh) +
            (tok0 + qt * 128 + row) * 3072 + qoff + ch * 8;
        cp16(sb + arr * FQ_B + row * 144 + ch * 16, src);
    }
    // KV loader: 2 arrays (K, V) x 64 rows x 8 chunks = 1024 -> 4/thread
    auto load_kv = [&](int kt, int s) {
        const uint32_t st = sb + 2 * FQ_B + s * KVS_B;
#pragma unroll
        for (int i = 0; i < 4; i++) {
            int idx = tid + i * 256;
            int arr = idx >> 9;
            int rem = idx & 511;
            int row = rem >> 3, ch = rem & 7;
            const __half* src = qh + (tok0 + kt * 64 + row) * 3072 +
                                (arr == 0 ? koff : voff) + ch * 8;
            cp16(st + arr * KV_B + row * 144 + ch * 16, src);
        }
    };

    load_kv(0, 0);
    CP_COMMIT();
    load_kv(1, 1);
    CP_COMMIT();
    CP_WAIT1();
    __syncthreads();

    // Q-hi fragments resident; Q-lo reloaded per tile via ldmatrix
    uint32_t qa_h[4][4];
    const int qrow = wid * 16;
    const uint32_t ql_u = sb + FQ_B;
    const uint32_t lrow16 = lane & 15;
    const uint32_t lcol8 = (lane >> 4) << 3;
    const uint32_t qfrag_off = (qrow + lrow16) * 144 + lcol8 * 2;
#pragma unroll
    for (int kap = 0; kap < 4; kap++) {
        int cb = kap * 16 + 2 * qq;
        qa_h[kap][0] = *(const uint32_t*)&Qh[(qrow + gr) * FP + cb];
        qa_h[kap][1] = *(const uint32_t*)&Qh[(qrow + gr + 8) * FP + cb];
        qa_h[kap][2] = *(const uint32_t*)&Qh[(qrow + gr) * FP + cb + 8];
        qa_h[kap][3] = *(const uint32_t*)&Qh[(qrow + gr + 8) * FP + cb + 8];
    }

    float m0 = -1e30f, m1 = -1e30f, l0 = 0.0f, l1 = 0.0f;
    float o[8][4] = {};

    for (int kt = 0; kt < 32; kt++) {
        const uint32_t st = sb + 2 * FQ_B + (kt & 1) * KVS_B;
        const uint32_t kh_u = st;
        const uint32_t vh_u = st + KV_B;

        // ---- S = Q @ K^T  (2-term: Qh·K + Ql·K, K single fp16) ----
        float S[8][4];
#pragma unroll
        for (int j = 0; j < 8; j++) { S[j][0] = S[j][1] = S[j][2] = S[j][3] = 0.0f; }
#pragma unroll
        for (int kap = 0; kap < 4; kap++) {
            uint32_t qa_l[4];
            ldm_x4(qa_l, ql_u + qfrag_off + kap * 32);
            const uint32_t koff2 = (kap * 16 + lcol8) * 2;
#pragma unroll
            for (int jp = 0; jp < 4; jp++) {
                uint32_t rh[4];
                ldm_x4(rh, kh_u + (jp * 16 + lrow16) * 144 + koff2);
                mma_f16(S[2 * jp],     qa_h[kap], rh[0], rh[2]);
                mma_f16(S[2 * jp + 1], qa_h[kap], rh[1], rh[3]);
                mma_f16(S[2 * jp],     qa_l, rh[0], rh[2]);
                mma_f16(S[2 * jp + 1], qa_l, rh[1], rh[3]);
            }
        }
#pragma unroll
        for (int j = 0; j < 8; j++) {
            S[j][0] *= QS; S[j][1] *= QS; S[j][2] *= QS; S[j][3] *= QS;
        }

        // ---- online softmax ----
        float t0 = -1e30f, t1 = -1e30f;
#pragma unroll
        for (int j = 0; j < 8; j++) {
            t0 = fmaxf(t0, fmaxf(S[j][0], S[j][1]));
            t1 = fmaxf(t1, fmaxf(S[j][2], S[j][3]));
        }
        t0 = fmaxf(t0, __shfl_xor_sync(0xffffffffu, t0, 1));
        t0 = fmaxf(t0, __shfl_xor_sync(0xffffffffu, t0, 2));
        t1 = fmaxf(t1, __shfl_xor_sync(0xffffffffu, t1, 1));
        t1 = fmaxf(t1, __shfl_xor_sync(0xffffffffu, t1, 2));
        float mn0 = fmaxf(m0, t0), mn1 = fmaxf(m1, t1);
        float al0 = ex2(m0 - mn0), al1 = ex2(m1 - mn1);
        m0 = mn0; m1 = mn1;

        float rs0 = 0.0f, rs1 = 0.0f;
#pragma unroll
        for (int j = 0; j < 8; j++) {
            S[j][0] = ex2(S[j][0] - m0);
            S[j][1] = ex2(S[j][1] - m0);
            S[j][2] = ex2(S[j][2] - m1);
            S[j][3] = ex2(S[j][3] - m1);
            rs0 += S[j][0] + S[j][1];
            rs1 += S[j][2] + S[j][3];
        }
        rs0 += __shfl_xor_sync(0xffffffffu, rs0, 1);
        rs0 += __shfl_xor_sync(0xffffffffu, rs0, 2);
        rs1 += __shfl_xor_sync(0xffffffffu, rs1, 1);
        rs1 += __shfl_xor_sync(0xffffffffu, rs1, 2);
        l0 = l0 * al0 + rs0;
        l1 = l1 * al1 + rs1;
#pragma unroll
        for (int jn = 0; jn < 8; jn++) {
            o[jn][0] *= al0; o[jn][1] *= al0;
            o[jn][2] *= al1; o[jn][3] *= al1;
        }

        // ---- split P into fp16 hi/lo A-fragments ----
        uint32_t ph[4][4], pl[4][4];
#pragma unroll
        for (int kap = 0; kap < 4; kap++) {
            const float* s0 = S[2 * kap];
            const float* s1 = S[2 * kap + 1];
            split2h(s0[0], s0[1], ph[kap][0], pl[kap][0]);
            split2h(s0[2], s0[3], ph[kap][1], pl[kap][1]);
            split2h(s1[0], s1[1], ph[kap][2], pl[kap][2]);
            split2h(s1[2], s1[3], ph[kap][3], pl[kap][3]);
        }

        // ---- O += P @ V  (2-term: Ph·V + Pl·V, V single fp16) ----
#pragma unroll
        for (int jn = 0; jn < 8; jn++) {
#pragma unroll
            for (int kp2 = 0; kp2 < 2; kp2++) {
                uint32_t vh4[4];
                ldm_x4_trans(vh4, vh_u + (kp2 * 32 + lane) * 144 + jn * 16);
                mma_f16(o[jn], ph[2 * kp2],     vh4[0], vh4[1]);
                mma_f16(o[jn], pl[2 * kp2],     vh4[0], vh4[1]);
                mma_f16(o[jn], ph[2 * kp2 + 1], vh4[2], vh4[3]);
                mma_f16(o[jn], pl[2 * kp2 + 1], vh4[2], vh4[3]);
            }
        }

        // ---- prefetch KV(kt+2) ----
        __syncthreads();
        if (kt + 2 < 32) load_kv(kt + 2, kt & 1);
        CP_COMMIT();
        if (kt + 1 < 32) {
            CP_WAIT1();
            __syncthreads();
        }
    }

    // ---- epilogue: normalize, split, store fp16 hi/lo (b, s, h*64+d) ----
    float inv0 = 1.0f / l0, inv1 = 1.0f / l1;
    const size_t row0 = (tok0 + qt * 128 + wid * 16 + gr) * 1024 + h * 64;
    const size_t row1 = row0 + 8 * 1024;
#pragma unroll
    for (int jn = 0; jn < 8; jn++) {
        int cc = jn * 8 + 2 * qq;
        uint32_t hi, lo;
        split2h(o[jn][0] * inv0, o[jn][1] * inv0, hi, lo);
        *(uint32_t*)&oh[row0 + cc] = hi;
        *(uint32_t*)&ol[row0 + cc] = lo;
        split2h(o[jn][2] * inv1, o[jn][3] * inv1, hi, lo);
        *(uint32_t*)&oh[row1 + cc] = hi;
        *(uint32_t*)&ol[row1 + cc] = lo;
    }
}

// ---------------------------------------------------------------------------
// Launch
// ---------------------------------------------------------------------------
extern "C" void kernel_launch(void* const* d_in, const int* in_sizes, int n_in,
                              void* d_out, int out_size) {
    const float* x     = (const float*)d_in[0];  // [2,2048,1024]
    const float* w_qkv = (const float*)d_in[1];  // [3072,1024]
    const float* w_out = (const float*)d_in[2];  // [1024,1024]
    float* out = (float*)d_out;                  // [2,2048,1024]

    __half *xh, *xl, *wq, *wo, *qh, *ql, *ah, *al;
    cudaGetSymbolAddress((void**)&xh, g_xh);  cudaGetSymbolAddress((void**)&xl, g_xl);
    cudaGetSymbolAddress((void**)&wq, g_wq);  cudaGetSymbolAddress((void**)&wo, g_wo);
    cudaGetSymbolAddress((void**)&qh, g_qh);  cudaGetSymbolAddress((void**)&ql, g_ql);
    cudaGetSymbolAddress((void**)&ah, g_ah);  cudaGetSymbolAddress((void**)&al, g_al);

    cudaFuncSetAttribute(flash_attn, cudaFuncAttributeMaxDynamicSharedMemorySize, FLASH_SMEM);
    cudaFuncSetAttribute(gemm_mma<true>, cudaFuncAttributeMaxDynamicSharedMemorySize, GEMM_SMEM);
    cudaFuncSetAttribute(gemm_mma<false>, cudaFuncAttributeMaxDynamicSharedMemorySize, GEMM_SMEM);

    dim3 blk(256);
    split_all<<<(X4 + W4 + O4) / 256, blk>>>(x, w_qkv, w_out, xh, xl, wq, wo);
    // QKV: [4096,3072] = (xh+xl) @ wq^T  -> fp16 hi/lo
    gemm_mma<true><<<dim3(3072 / 128, 4096 / 128), blk, GEMM_SMEM>>>(
        xh, xl, wq, nullptr, qh, ql, 1024, 3072);
    // Attention -> fp16 hi/lo
    flash_attn<<<dim3(16, 32), blk, FLASH_SMEM>>>(qh, ql, ah, al);
    // Out: [4096,1024] = (ah+al) @ wo^T -> fp32
    gemm_mma<false><<<dim3(1024 / 128, 4096 / 128), blk, GEMM_SMEM>>>(
        ah, al, wo, out, nullptr, nullptr, 1024, 1024);
}

// round 16
// speedup vs baseline: 2.6530x; 1.7231x over previous
#include <cuda_runtime.h>
#include <cuda_fp16.h>
#include <math.h>
#include <stdint.h>

// ---------------------------------------------------------------------------
// Scratch (allocation-free rule: device globals)  — single fp16 everywhere
// ---------------------------------------------------------------------------
__device__ __half g_x[4096 * 1024];     // x fp16
__device__ __half g_wq[3072 * 1024];    // w_qkv fp16
__device__ __half g_wo[1024 * 1024];    // w_out fp16
__device__ __half g_q[4096 * 3072];     // qkv fp16
__device__ __half g_a[4096 * 1024];     // attn fp16

// ---------------------------------------------------------------------------
// Helpers
// ---------------------------------------------------------------------------
__device__ __forceinline__ uint32_t smem_u32(const void* p) {
    uint32_t a;
    asm("{ .reg .u64 t; cvta.to.shared.u64 t, %1; cvt.u32.u64 %0, t; }" : "=r"(a) : "l"(p));
    return a;
}
__device__ __forceinline__ float ex2(float x) {
    float r; asm("ex2.approx.f32 %0, %1;" : "=f"(r) : "f"(x)); return r;
}
__device__ __forceinline__ uint32_t packh(float x, float y) {
    uint32_t h;
    asm("cvt.rn.f16x2.f32 %0, %1, %2;" : "=r"(h) : "f"(y), "f"(x));
    return h;
}
__device__ __forceinline__ void mma_f16(float c[4], const uint32_t a[4],
                                        uint32_t b0, uint32_t b1) {
    asm volatile(
        "mma.sync.aligned.m16n8k16.row.col.f32.f16.f16.f32 "
        "{%0,%1,%2,%3}, {%4,%5,%6,%7}, {%8,%9}, {%0,%1,%2,%3};"
        : "+f"(c[0]), "+f"(c[1]), "+f"(c[2]), "+f"(c[3])
        : "r"(a[0]), "r"(a[1]), "r"(a[2]), "r"(a[3]), "r"(b0), "r"(b1));
}
__device__ __forceinline__ void ldm_x4(uint32_t r[4], uint32_t addr) {
    asm volatile("ldmatrix.sync.aligned.m8n8.x4.shared.b16 {%0,%1,%2,%3}, [%4];"
                 : "=r"(r[0]), "=r"(r[1]), "=r"(r[2]), "=r"(r[3]) : "r"(addr));
}
__device__ __forceinline__ void ldm_x4_trans(uint32_t r[4], uint32_t addr) {
    asm volatile("ldmatrix.sync.aligned.m8n8.x4.trans.shared.b16 {%0,%1,%2,%3}, [%4];"
                 : "=r"(r[0]), "=r"(r[1]), "=r"(r[2]), "=r"(r[3]) : "r"(addr));
}
__device__ __forceinline__ void cp16(uint32_t saddr, const void* g) {
    asm volatile("cp.async.cg.shared.global [%0], [%1], 16;" :: "r"(saddr), "l"(g));
}
#define CP_COMMIT() asm volatile("cp.async.commit_group;" ::: "memory")
#define CP_WAIT1()  asm volatile("cp.async.wait_group 1;" ::: "memory")

// ---------------------------------------------------------------------------
// fused convert kernel: all three fp32 inputs -> single fp16
// ---------------------------------------------------------------------------
#define X4 (4096 * 1024 / 4)
#define W4 (3072 * 1024 / 4)
#define O4 (1024 * 1024 / 4)

__global__ void conv_all(const float* __restrict__ x,
                         const float* __restrict__ wq,
                         const float* __restrict__ wo,
                         __half* __restrict__ xh,
                         __half* __restrict__ wqh,
                         __half* __restrict__ woh) {
    int i = blockIdx.x * blockDim.x + threadIdx.x;
    float4 v;
    uint2 h;
    if (i < X4) {
        v = ((const float4*)x)[i];
        h.x = packh(v.x, v.y); h.y = packh(v.z, v.w);
        ((uint2*)xh)[i] = h;
    } else if (i < X4 + W4) {
        int j = i - X4;
        v = ((const float4*)wq)[j];
        h.x = packh(v.x, v.y); h.y = packh(v.z, v.w);
        ((uint2*)wqh)[j] = h;
    } else {
        int j = i - X4 - W4;
        v = ((const float4*)wo)[j];
        h.x = packh(v.x, v.y); h.y = packh(v.z, v.w);
        ((uint2*)woh)[j] = h;
    }
}

// ---------------------------------------------------------------------------
// plain fp16 GEMM (fp32 accum):  C[M,N] = A[M,K] @ B[N,K]^T
// mma.sync + XOR-swizzled smem + 3-stage cp.async, one barrier/chunk, 2 CTA/SM.
// Epilogue: fp32 C or packed fp16 Ch.
// ---------------------------------------------------------------------------
#define ARR_B  8192                  // 128 rows x 64 B (32 fp16)
#define STG_B  (2 * ARR_B)           // A B = 16384
#define NSTG   3
#define GEMM_SMEM (NSTG * STG_B)     // 49152 -> 2 CTAs/SM

template <bool PACKC>
__global__ __launch_bounds__(256, 2) void gemm_mma(const __half* __restrict__ Ag,
                                                   const __half* __restrict__ Bg,
                                                   float* __restrict__ C,
                                                   __half* __restrict__ Ch,
                                                   int K, int N) {
    extern __shared__ __align__(16) char gsm[];
    const uint32_t sbase = smem_u32(gsm);

    const int tid = threadIdx.x;
    const int wid = tid >> 5;
    const int lane = tid & 31;
    const int wr = wid >> 2;
    const int wc = wid & 3;
    const int gr = lane >> 2, qq = lane & 3;
    const int row0 = blockIdx.y * 128;
    const int col0 = blockIdx.x * 128;
    const int NCH = K >> 5;

    // writer: 2 arrays x 128 rows x 4 chunks = 1024 cp16 -> 4 per thread
    auto load_chunk = [&](int kc, int stg) {
        const uint32_t st = sbase + stg * STG_B;
#pragma unroll
        for (int t = 0; t < 4; t++) {
            int idx = tid + t * 256;
            int arr = idx >> 9;
            int rem = idx & 511;
            int row = rem >> 2;
            int ch = rem & 3;
            uint32_t sa = st + arr * ARR_B + row * 64 + ((ch ^ ((row >> 1) & 3)) << 4);
            const __half* gp;
            int kcol = kc * 32 + ch * 8;
            if (arr == 0) gp = &Ag[(size_t)(row0 + row) * K + kcol];
            else          gp = &Bg[(size_t)(col0 + row) * K + kcol];
            cp16(sa, gp);
        }
    };

    float acc[4][4][4] = {};

    load_chunk(0, 0);
    CP_COMMIT();
    load_chunk(1, 1);
    CP_COMMIT();

    const uint32_t lrow = lane & 15;
    const int kbase = lane >> 4;
    const uint32_t sw = (lrow >> 1) & 3;
    uint32_t aoff[4], boff[2];
#pragma unroll
    for (int i = 0; i < 4; i++) aoff[i] = (wr * 64 + i * 16 + lrow) * 64;
#pragma unroll
    for (int g = 0; g < 2; g++) boff[g] = (wc * 32 + g * 16 + lrow) * 64;

    for (int c = 0; c < NCH; c++) {
        CP_WAIT1();
        __syncthreads();
        int nc = c + 2;
        if (nc < NCH) load_chunk(nc, nc % 3);
        CP_COMMIT();

        const uint32_t st = sbase + (c % 3) * STG_B;
        const uint32_t ah = st, bh = st + ARR_B;
#pragma unroll
        for (int ks = 0; ks < 2; ks++) {
            const uint32_t scol = (uint32_t)(((ks * 2 + kbase) ^ sw) << 4);
            uint32_t fa[4][4], fb[4][2];
#pragma unroll
            for (int i = 0; i < 4; i++)
                ldm_x4(fa[i], ah + aoff[i] + scol);
#pragma unroll
            for (int g = 0; g < 2; g++) {
                uint32_t r[4];
                ldm_x4(r, bh + boff[g] + scol);
                fb[2 * g][0] = r[0]; fb[2 * g][1] = r[2];
                fb[2 * g + 1][0] = r[1]; fb[2 * g + 1][1] = r[3];
            }
#pragma unroll
            for (int i = 0; i < 4; i++)
#pragma unroll
                for (int j = 0; j < 4; j++)
                    mma_f16(acc[i][j], fa[i], fb[j][0], fb[j][1]);
        }
    }

    // epilogue
#pragma unroll
    for (int i = 0; i < 4; i++) {
        int r0g = row0 + wr * 64 + i * 16 + gr;
#pragma unroll
        for (int j = 0; j < 4; j++) {
            int cg = col0 + wc * 32 + j * 8 + 2 * qq;
            if (PACKC) {
                *(uint32_t*)&Ch[(size_t)r0g * N + cg] = packh(acc[i][j][0], acc[i][j][1]);
                *(uint32_t*)&Ch[(size_t)(r0g + 8) * N + cg] = packh(acc[i][j][2], acc[i][j][3]);
            } else {
                *(float2*)&C[(size_t)r0g * N + cg] = make_float2(acc[i][j][0], acc[i][j][1]);
                *(float2*)&C[(size_t)(r0g + 8) * N + cg] = make_float2(acc[i][j][2], acc[i][j][3]);
            }
        }
    }
}

// ---------------------------------------------------------------------------
// Flash attention, pure fp16 operands (fp32 accum/softmax state).
// cp.async double-buffer; KV stage = {K, V}. 128 q-rows x (b,h), 8 warps.
// ---------------------------------------------------------------------------
#define FP     72                       // fp16 row pitch (144 B)
#define FQ_B   (128 * FP * 2)           // Q array bytes (18432)
#define KV_B   (64 * FP * 2)            // per-array bytes (9216)
#define KVS_B  (2 * KV_B)               // KV stage: K V = 18432
#define FLASH_SMEM (FQ_B + 2 * KVS_B)   // 55296

__global__ __launch_bounds__(256, 2) void flash_attn(const __half* __restrict__ qkv,
                                                     __half* __restrict__ attn) {
    extern __shared__ __align__(16) char fsmc[];
    const uint32_t sb = smem_u32(fsmc);
    __half* Qs = (__half*)fsmc;

    const int tid = threadIdx.x;
    const int wid = tid >> 5;
    const int lane = tid & 31;
    const int gr = lane >> 2;
    const int qq = lane & 3;

    const int qt = blockIdx.x;
    const int b  = blockIdx.y >> 4;
    const int h  = blockIdx.y & 15;

    const size_t tok0 = (size_t)b * 2048;
    const int qoff = h * 64, koff = 1024 + h * 64, voff = 2048 + h * 64;
    const float QS = 0.125f * 1.4426950408889634f;   // 1/sqrt(64) * log2(e)

    // ---- async load Q (128 rows x 8 chunks = 1024 -> 4/thread) ----
#pragma unroll
    for (int i = 0; i < 4; i++) {
        int idx = tid + i * 256;
        int row = idx >> 3, ch = idx & 7;
        const __half* src = qkv + (tok0 + qt * 128 + row) * 3072 + qoff + ch * 8;
        cp16(sb + row * 144 + ch * 16, src);
    }
    // KV loader: 2 arrays (K, V) x 64 rows x 8 chunks = 1024 -> 4/thread
    auto load_kv = [&](int kt, int s) {
        const uint32_t st = sb + FQ_B + s * KVS_B;
#pragma unroll
        for (int i = 0; i < 4; i++) {
            int idx = tid + i * 256;
            int arr = idx >> 9;
            int rem = idx & 511;
            int row = rem >> 3, ch = rem & 7;
            const __half* src = qkv + (tok0 + kt * 64 + row) * 3072 +
                                (arr == 0 ? koff : voff) + ch * 8;
            cp16(st + arr * KV_B + row * 144 + ch * 16, src);
        }
    };

    load_kv(0, 0);
    CP_COMMIT();
    load_kv(1, 1);
    CP_COMMIT();
    CP_WAIT1();
    __syncthreads();

    // Q A-fragments resident in regs
    uint32_t qa[4][4];
    const int qrow = wid * 16;
    const uint32_t lrow16 = lane & 15;
    const uint32_t lcol8 = (lane >> 4) << 3;
#pragma unroll
    for (int kap = 0; kap < 4; kap++) {
        int cb = kap * 16 + 2 * qq;
        qa[kap][0] = *(const uint32_t*)&Qs[(qrow + gr) * FP + cb];
        qa[kap][1] = *(const uint32_t*)&Qs[(qrow + gr + 8) * FP + cb];
        qa[kap][2] = *(const uint32_t*)&Qs[(qrow + gr) * FP + cb + 8];
        qa[kap][3] = *(const uint32_t*)&Qs[(qrow + gr + 8) * FP + cb + 8];
    }

    float m0 = -1e30f, m1 = -1e30f, l0 = 0.0f, l1 = 0.0f;
    float o[8][4] = {};

    for (int kt = 0; kt < 32; kt++) {
        const uint32_t st = sb + FQ_B + (kt & 1) * KVS_B;
        const uint32_t kh_u = st;
        const uint32_t vh_u = st + KV_B;

        // ---- S = Q @ K^T (single-term fp16) ----
        float S[8][4];
#pragma unroll
        for (int j = 0; j < 8; j++) { S[j][0] = S[j][1] = S[j][2] = S[j][3] = 0.0f; }
#pragma unroll
        for (int kap = 0; kap < 4; kap++) {
            const uint32_t koff2 = (kap * 16 + lcol8) * 2;
#pragma unroll
            for (int jp = 0; jp < 4; jp++) {
                uint32_t rh[4];
                ldm_x4(rh, kh_u + (jp * 16 + lrow16) * 144 + koff2);
                mma_f16(S[2 * jp],     qa[kap], rh[0], rh[2]);
                mma_f16(S[2 * jp + 1], qa[kap], rh[1], rh[3]);
            }
        }
#pragma unroll
        for (int j = 0; j < 8; j++) {
            S[j][0] *= QS; S[j][1] *= QS; S[j][2] *= QS; S[j][3] *= QS;
        }

        // ---- online softmax ----
        float t0 = -1e30f, t1 = -1e30f;
#pragma unroll
        for (int j = 0; j < 8; j++) {
            t0 = fmaxf(t0, fmaxf(S[j][0], S[j][1]));
            t1 = fmaxf(t1, fmaxf(S[j][2], S[j][3]));
        }
        t0 = fmaxf(t0, __shfl_xor_sync(0xffffffffu, t0, 1));
        t0 = fmaxf(t0, __shfl_xor_sync(0xffffffffu, t0, 2));
        t1 = fmaxf(t1, __shfl_xor_sync(0xffffffffu, t1, 1));
        t1 = fmaxf(t1, __shfl_xor_sync(0xffffffffu, t1, 2));
        float mn0 = fmaxf(m0, t0), mn1 = fmaxf(m1, t1);
        float al0 = ex2(m0 - mn0), al1 = ex2(m1 - mn1);
        m0 = mn0; m1 = mn1;

        float rs0 = 0.0f, rs1 = 0.0f;
#pragma unroll
        for (int j = 0; j < 8; j++) {
            S[j][0] = ex2(S[j][0] - m0);
            S[j][1] = ex2(S[j][1] - m0);
            S[j][2] = ex2(S[j][2] - m1);
            S[j][3] = ex2(S[j][3] - m1);
            rs0 += S[j][0] + S[j][1];
            rs1 += S[j][2] + S[j][3];
        }
        rs0 += __shfl_xor_sync(0xffffffffu, rs0, 1);
        rs0 += __shfl_xor_sync(0xffffffffu, rs0, 2);
        rs1 += __shfl_xor_sync(0xffffffffu, rs1, 1);
        rs1 += __shfl_xor_sync(0xffffffffu, rs1, 2);
        l0 = l0 * al0 + rs0;
        l1 = l1 * al1 + rs1;
#pragma unroll
        for (int jn = 0; jn < 8; jn++) {
            o[jn][0] *= al0; o[jn][1] *= al0;
            o[jn][2] *= al1; o[jn][3] *= al1;
        }

        // ---- pack P to fp16 A-fragments (single) ----
        uint32_t ph[4][4];
#pragma unroll
        for (int kap = 0; kap < 4; kap++) {
            const float* s0 = S[2 * kap];
            const float* s1 = S[2 * kap + 1];
            ph[kap][0] = packh(s0[0], s0[1]);
            ph[kap][1] = packh(s0[2], s0[3]);
            ph[kap][2] = packh(s1[0], s1[1]);
            ph[kap][3] = packh(s1[2], s1[3]);
        }

        // ---- O += P @ V (single-term) ----
#pragma unroll
        for (int jn = 0; jn < 8; jn++) {
#pragma unroll
            for (int kp2 = 0; kp2 < 2; kp2++) {
                uint32_t vh4[4];
                ldm_x4_trans(vh4, vh_u + (kp2 * 32 + lane) * 144 + jn * 16);
                mma_f16(o[jn], ph[2 * kp2],     vh4[0], vh4[1]);
                mma_f16(o[jn], ph[2 * kp2 + 1], vh4[2], vh4[3]);
            }
        }

        // ---- prefetch KV(kt+2) ----
        __syncthreads();
        if (kt + 2 < 32) load_kv(kt + 2, kt & 1);
        CP_COMMIT();
        if (kt + 1 < 32) {
            CP_WAIT1();
            __syncthreads();
        }
    }

    // ---- epilogue: normalize, pack fp16, store (b, s, h*64+d) ----
    float inv0 = 1.0f / l0, inv1 = 1.0f / l1;
    const size_t row0 = (tok0 + qt * 128 + wid * 16 + gr) * 1024 + h * 64;
    const size_t row1 = row0 + 8 * 1024;
#pragma unroll
    for (int jn = 0; jn < 8; jn++) {
        int cc = jn * 8 + 2 * qq;
        *(uint32_t*)&attn[row0 + cc] = packh(o[jn][0] * inv0, o[jn][1] * inv0);
        *(uint32_t*)&attn[row1 + cc] = packh(o[jn][2] * inv1, o[jn][3] * inv1);
    }
}

// ---------------------------------------------------------------------------
// Launch: convert -> QKV GEMM (fp16 out) -> flash (fp16 out) -> out GEMM (fp32)
// ---------------------------------------------------------------------------
extern "C" void kernel_launch(void* const* d_in, const int* in_sizes, int n_in,
                              void* d_out, int out_size) {
    const float* x     = (const float*)d_in[0];  // [2,2048,1024]
    const float* w_qkv = (const float*)d_in[1];  // [3072,1024]
    const float* w_out = (const float*)d_in[2];  // [1024,1024]
    float* out = (float*)d_out;                  // [2,2048,1024]

    __half *xh, *wq, *wo, *qh, *ah;
    cudaGetSymbolAddress((void**)&xh, g_x);
    cudaGetSymbolAddress((void**)&wq, g_wq);
    cudaGetSymbolAddress((void**)&wo, g_wo);
    cudaGetSymbolAddress((void**)&qh, g_q);
    cudaGetSymbolAddress((void**)&ah, g_a);

    cudaFuncSetAttribute(flash_attn, cudaFuncAttributeMaxDynamicSharedMemorySize, FLASH_SMEM);
    cudaFuncSetAttribute(gemm_mma<true>, cudaFuncAttributeMaxDynamicSharedMemorySize, GEMM_SMEM);
    cudaFuncSetAttribute(gemm_mma<false>, cudaFuncAttributeMaxDynamicSharedMemorySize, GEMM_SMEM);

    dim3 blk(256);
    conv_all<<<(X4 + W4 + O4) / 256, blk>>>(x, w_qkv, w_out, xh, wq, wo);
    // QKV: [4096,3072] = x @ wq^T  -> fp16
    gemm_mma<true><<<dim3(3072 / 128, 4096 / 128), blk, GEMM_SMEM>>>(
        xh, wq, nullptr, qh, 1024, 3072);
    // Attention -> fp16
    flash_attn<<<dim3(16, 32), blk, FLASH_SMEM>>>(qh, ah);
    // Out: [4096,1024] = attn @ wo^T -> fp32
    gemm_mma<false><<<dim3(1024 / 128, 4096 / 128), blk, GEMM_SMEM>>>(
        ah, wo, out, nullptr, 1024, 1024);
}

// round 17
// speedup vs baseline: 2.6757x; 1.0086x over previous
#include <cuda_runtime.h>
#include <cuda_fp16.h>
#include <math.h>
#include <stdint.h>

// ---------------------------------------------------------------------------
// Scratch (allocation-free rule: device globals)  — single fp16 everywhere
// ---------------------------------------------------------------------------
__device__ __half g_x[4096 * 1024];     // x fp16
__device__ __half g_wq[3072 * 1024];    // w_qkv fp16
__device__ __half g_wo[1024 * 1024];    // w_out fp16
__device__ __half g_q[4096 * 3072];     // qkv fp16
__device__ __half g_a[4096 * 1024];     // attn fp16

// ---------------------------------------------------------------------------
// Helpers
// ---------------------------------------------------------------------------
__device__ __forceinline__ uint32_t smem_u32(const void* p) {
    uint32_t a;
    asm("{ .reg .u64 t; cvta.to.shared.u64 t, %1; cvt.u32.u64 %0, t; }" : "=r"(a) : "l"(p));
    return a;
}
__device__ __forceinline__ float ex2(float x) {
    float r; asm("ex2.approx.f32 %0, %1;" : "=f"(r) : "f"(x)); return r;
}
__device__ __forceinline__ uint32_t packh(float x, float y) {
    uint32_t h;
    asm("cvt.rn.f16x2.f32 %0, %1, %2;" : "=r"(h) : "f"(y), "f"(x));
    return h;
}
__device__ __forceinline__ void mma_f16(float c[4], const uint32_t a[4],
                                        uint32_t b0, uint32_t b1) {
    asm volatile(
        "mma.sync.aligned.m16n8k16.row.col.f32.f16.f16.f32 "
        "{%0,%1,%2,%3}, {%4,%5,%6,%7}, {%8,%9}, {%0,%1,%2,%3};"
        : "+f"(c[0]), "+f"(c[1]), "+f"(c[2]), "+f"(c[3])
        : "r"(a[0]), "r"(a[1]), "r"(a[2]), "r"(a[3]), "r"(b0), "r"(b1));
}
__device__ __forceinline__ void ldm_x4(uint32_t r[4], uint32_t addr) {
    asm volatile("ldmatrix.sync.aligned.m8n8.x4.shared.b16 {%0,%1,%2,%3}, [%4];"
                 : "=r"(r[0]), "=r"(r[1]), "=r"(r[2]), "=r"(r[3]) : "r"(addr));
}
__device__ __forceinline__ void ldm_x4_trans(uint32_t r[4], uint32_t addr) {
    asm volatile("ldmatrix.sync.aligned.m8n8.x4.trans.shared.b16 {%0,%1,%2,%3}, [%4];"
                 : "=r"(r[0]), "=r"(r[1]), "=r"(r[2]), "=r"(r[3]) : "r"(addr));
}
__device__ __forceinline__ void cp16(uint32_t saddr, const void* g) {
    asm volatile("cp.async.cg.shared.global [%0], [%1], 16;" :: "r"(saddr), "l"(g));
}
#define CP_COMMIT() asm volatile("cp.async.commit_group;" ::: "memory")
#define CP_WAIT1()  asm volatile("cp.async.wait_group 1;" ::: "memory")
#define CP_WAIT2()  asm volatile("cp.async.wait_group 2;" ::: "memory")

// ---------------------------------------------------------------------------
// fused convert kernel: all three fp32 inputs -> single fp16
// ---------------------------------------------------------------------------
#define X4 (4096 * 1024 / 4)
#define W4 (3072 * 1024 / 4)
#define O4 (1024 * 1024 / 4)

__global__ void conv_all(const float* __restrict__ x,
                         const float* __restrict__ wq,
                         const float* __restrict__ wo,
                         __half* __restrict__ xh,
                         __half* __restrict__ wqh,
                         __half* __restrict__ woh) {
    int i = blockIdx.x * blockDim.x + threadIdx.x;
    float4 v;
    uint2 h;
    if (i < X4) {
        v = ((const float4*)x)[i];
        h.x = packh(v.x, v.y); h.y = packh(v.z, v.w);
        ((uint2*)xh)[i] = h;
    } else if (i < X4 + W4) {
        int j = i - X4;
        v = ((const float4*)wq)[j];
        h.x = packh(v.x, v.y); h.y = packh(v.z, v.w);
        ((uint2*)wqh)[j] = h;
    } else {
        int j = i - X4 - W4;
        v = ((const float4*)wo)[j];
        h.x = packh(v.x, v.y); h.y = packh(v.z, v.w);
        ((uint2*)woh)[j] = h;
    }
}

// ---------------------------------------------------------------------------
// plain fp16 GEMM (fp32 accum):  C[M,N] = A[M,K] @ B[N,K]^T
// mma.sync + XOR-swizzled smem + 4-stage cp.async (3 loads in flight),
// one barrier per 32-K chunk, 2 CTAs/SM.
// ---------------------------------------------------------------------------
#define ARR_B  8192                  // 128 rows x 64 B (32 fp16)
#define STG_B  (2 * ARR_B)           // A B = 16384
#define NSTG   4
#define GEMM_SMEM (NSTG * STG_B)     // 65536 -> 2 CTAs/SM

template <bool PACKC>
__global__ __launch_bounds__(256, 2) void gemm_mma(const __half* __restrict__ Ag,
                                                   const __half* __restrict__ Bg,
                                                   float* __restrict__ C,
                                                   __half* __restrict__ Ch,
                                                   int K, int N) {
    extern __shared__ __align__(16) char gsm[];
    const uint32_t sbase = smem_u32(gsm);

    const int tid = threadIdx.x;
    const int wid = tid >> 5;
    const int lane = tid & 31;
    const int wr = wid >> 2;
    const int wc = wid & 3;
    const int gr = lane >> 2, qq = lane & 3;
    const int row0 = blockIdx.y * 128;
    const int col0 = blockIdx.x * 128;
    const int NCH = K >> 5;

    auto load_chunk = [&](int kc, int stg) {
        const uint32_t st = sbase + stg * STG_B;
#pragma unroll
        for (int t = 0; t < 4; t++) {
            int idx = tid + t * 256;
            int arr = idx >> 9;
            int rem = idx & 511;
            int row = rem >> 2;
            int ch = rem & 3;
            uint32_t sa = st + arr * ARR_B + row * 64 + ((ch ^ ((row >> 1) & 3)) << 4);
            const __half* gp;
            int kcol = kc * 32 + ch * 8;
            if (arr == 0) gp = &Ag[(size_t)(row0 + row) * K + kcol];
            else          gp = &Bg[(size_t)(col0 + row) * K + kcol];
            cp16(sa, gp);
        }
    };

    float acc[4][4][4] = {};

    load_chunk(0, 0); CP_COMMIT();
    load_chunk(1, 1); CP_COMMIT();
    load_chunk(2, 2); CP_COMMIT();

    const uint32_t lrow = lane & 15;
    const int kbase = lane >> 4;
    const uint32_t sw = (lrow >> 1) & 3;
    uint32_t aoff[4], boff[2];
#pragma unroll
    for (int i = 0; i < 4; i++) aoff[i] = (wr * 64 + i * 16 + lrow) * 64;
#pragma unroll
    for (int g = 0; g < 2; g++) boff[g] = (wc * 32 + g * 16 + lrow) * 64;

    for (int c = 0; c < NCH; c++) {
        CP_WAIT2();            // chunk c landed (c+1, c+2 may still fly)
        __syncthreads();       // all warps done with stage (c+3)%4's old contents
        int nc = c + 3;
        if (nc < NCH) load_chunk(nc, nc & 3);
        CP_COMMIT();

        const uint32_t st = sbase + (c & 3) * STG_B;
        const uint32_t ah = st, bh = st + ARR_B;
#pragma unroll
        for (int ks = 0; ks < 2; ks++) {
            const uint32_t scol = (uint32_t)(((ks * 2 + kbase) ^ sw) << 4);
            uint32_t fa[4][4], fb[4][2];
#pragma unroll
            for (int i = 0; i < 4; i++)
                ldm_x4(fa[i], ah + aoff[i] + scol);
#pragma unroll
            for (int g = 0; g < 2; g++) {
                uint32_t r[4];
                ldm_x4(r, bh + boff[g] + scol);
                fb[2 * g][0] = r[0]; fb[2 * g][1] = r[2];
                fb[2 * g + 1][0] = r[1]; fb[2 * g + 1][1] = r[3];
            }
#pragma unroll
            for (int i = 0; i < 4; i++)
#pragma unroll
                for (int j = 0; j < 4; j++)
                    mma_f16(acc[i][j], fa[i], fb[j][0], fb[j][1]);
        }
    }

    // epilogue
#pragma unroll
    for (int i = 0; i < 4; i++) {
        int r0g = row0 + wr * 64 + i * 16 + gr;
#pragma unroll
        for (int j = 0; j < 4; j++) {
            int cg = col0 + wc * 32 + j * 8 + 2 * qq;
            if (PACKC) {
                *(uint32_t*)&Ch[(size_t)r0g * N + cg] = packh(acc[i][j][0], acc[i][j][1]);
                *(uint32_t*)&Ch[(size_t)(r0g + 8) * N + cg] = packh(acc[i][j][2], acc[i][j][3]);
            } else {
                *(float2*)&C[(size_t)r0g * N + cg] = make_float2(acc[i][j][0], acc[i][j][1]);
                *(float2*)&C[(size_t)(r0g + 8) * N + cg] = make_float2(acc[i][j][2], acc[i][j][3]);
            }
        }
    }
}

// ---------------------------------------------------------------------------
// Flash attention, pure fp16 operands (fp32 accum/softmax state).
// 128-key tiles (16 iterations): halves per-tile softmax/shuffle/barrier cost.
// Q-fragments reloaded from smem per tile (frees regs for S[16][4]).
// cp.async double-buffer; KV stage = {K, V} of 128 rows each.
// ---------------------------------------------------------------------------
#define FP     72                       // fp16 row pitch (144 B)
#define FQ_B   (128 * FP * 2)           // Q array bytes (18432)
#define KV_B   (128 * FP * 2)           // per-array bytes (18432)
#define KVS_B  (2 * KV_B)               // KV stage: K V = 36864
#define FLASH_SMEM (FQ_B + 2 * KVS_B)   // 92160 -> 2 CTAs/SM

__global__ __launch_bounds__(256, 2) void flash_attn(const __half* __restrict__ qkv,
                                                     __half* __restrict__ attn) {
    extern __shared__ __align__(16) char fsmc[];
    const uint32_t sb = smem_u32(fsmc);

    const int tid = threadIdx.x;
    const int wid = tid >> 5;
    const int lane = tid & 31;
    const int gr = lane >> 2;
    const int qq = lane & 3;

    const int qt = blockIdx.x;
    const int b  = blockIdx.y >> 4;
    const int h  = blockIdx.y & 15;

    const size_t tok0 = (size_t)b * 2048;
    const int qoff = h * 64, koff = 1024 + h * 64, voff = 2048 + h * 64;
    const float QS = 0.125f * 1.4426950408889634f;   // 1/sqrt(64) * log2(e)

    // ---- async load Q (128 rows x 8 chunks = 1024 -> 4/thread) ----
#pragma unroll
    for (int i = 0; i < 4; i++) {
        int idx = tid + i * 256;
        int row = idx >> 3, ch = idx & 7;
        const __half* src = qkv + (tok0 + qt * 128 + row) * 3072 + qoff + ch * 8;
        cp16(sb + row * 144 + ch * 16, src);
    }
    // KV loader: 2 arrays (K, V) x 128 rows x 8 chunks = 2048 -> 8/thread
    auto load_kv = [&](int kt, int s) {
        const uint32_t st = sb + FQ_B + s * KVS_B;
#pragma unroll
        for (int i = 0; i < 8; i++) {
            int idx = tid + i * 256;
            int arr = idx >> 10;
            int rem = idx & 1023;
            int row = rem >> 3, ch = rem & 7;
            const __half* src = qkv + (tok0 + kt * 128 + row) * 3072 +
                                (arr == 0 ? koff : voff) + ch * 8;
            cp16(st + arr * KV_B + row * 144 + ch * 16, src);
        }
    };

    load_kv(0, 0);
    CP_COMMIT();
    load_kv(1, 1);
    CP_COMMIT();
    CP_WAIT1();
    __syncthreads();

    const int qrow = wid * 16;
    const uint32_t lrow16 = lane & 15;
    const uint32_t lcol8 = (lane >> 4) << 3;
    const uint32_t qfrag_off = (qrow + lrow16) * 144 + lcol8 * 2;   // Q at smem base 0

    float m0 = -1e30f, m1 = -1e30f, l0 = 0.0f, l1 = 0.0f;
    float o[8][4] = {};

    for (int kt = 0; kt < 16; kt++) {
        const uint32_t st = sb + FQ_B + (kt & 1) * KVS_B;
        const uint32_t kh_u = st;
        const uint32_t vh_u = st + KV_B;

        // ---- S = Q @ K^T  (16 n8-blocks over 128 keys) ----
        float S[16][4];
#pragma unroll
        for (int j = 0; j < 16; j++) { S[j][0] = S[j][1] = S[j][2] = S[j][3] = 0.0f; }
#pragma unroll
        for (int kap = 0; kap < 4; kap++) {
            uint32_t qa[4];
            ldm_x4(qa, sb + qfrag_off + kap * 32);
            const uint32_t koff2 = (kap * 16 + lcol8) * 2;
#pragma unroll
            for (int jp = 0; jp < 8; jp++) {
                uint32_t rh[4];
                ldm_x4(rh, kh_u + (jp * 16 + lrow16) * 144 + koff2);
                mma_f16(S[2 * jp],     qa, rh[0], rh[2]);
                mma_f16(S[2 * jp + 1], qa, rh[1], rh[3]);
            }
        }
#pragma unroll
        for (int j = 0; j < 16; j++) {
            S[j][0] *= QS; S[j][1] *= QS; S[j][2] *= QS; S[j][3] *= QS;
        }

        // ---- online softmax ----
        float t0 = -1e30f, t1 = -1e30f;
#pragma unroll
        for (int j = 0; j < 16; j++) {
            t0 = fmaxf(t0, fmaxf(S[j][0], S[j][1]));
            t1 = fmaxf(t1, fmaxf(S[j][2], S[j][3]));
        }
        t0 = fmaxf(t0, __shfl_xor_sync(0xffffffffu, t0, 1));
        t0 = fmaxf(t0, __shfl_xor_sync(0xffffffffu, t0, 2));
        t1 = fmaxf(t1, __shfl_xor_sync(0xffffffffu, t1, 1));
        t1 = fmaxf(t1, __shfl_xor_sync(0xffffffffu, t1, 2));
        float mn0 = fmaxf(m0, t0), mn1 = fmaxf(m1, t1);
        float al0 = ex2(m0 - mn0), al1 = ex2(m1 - mn1);
        m0 = mn0; m1 = mn1;

        float rs0 = 0.0f, rs1 = 0.0f;
#pragma unroll
        for (int j = 0; j < 16; j++) {
            S[j][0] = ex2(S[j][0] - m0);
            S[j][1] = ex2(S[j][1] - m0);
            S[j][2] = ex2(S[j][2] - m1);
            S[j][3] = ex2(S[j][3] - m1);
            rs0 += S[j][0] + S[j][1];
            rs1 += S[j][2] + S[j][3];
        }
        rs0 += __shfl_xor_sync(0xffffffffu, rs0, 1);
        rs0 += __shfl_xor_sync(0xffffffffu, rs0, 2);
        rs1 += __shfl_xor_sync(0xffffffffu, rs1, 1);
        rs1 += __shfl_xor_sync(0xffffffffu, rs1, 2);
        l0 = l0 * al0 + rs0;
        l1 = l1 * al1 + rs1;
#pragma unroll
        for (int jn = 0; jn < 8; jn++) {
            o[jn][0] *= al0; o[jn][1] *= al0;
            o[jn][2] *= al1; o[jn][3] *= al1;
        }

        // ---- O += P @ V  (pack P per 32-key group; V via ldmatrix.x4.trans) ----
#pragma unroll
        for (int kp4 = 0; kp4 < 4; kp4++) {
            uint32_t ph0[4], ph1[4];
            {
                const float* s0 = S[4 * kp4];
                const float* s1 = S[4 * kp4 + 1];
                ph0[0] = packh(s0[0], s0[1]); ph0[1] = packh(s0[2], s0[3]);
                ph0[2] = packh(s1[0], s1[1]); ph0[3] = packh(s1[2], s1[3]);
                const float* s2 = S[4 * kp4 + 2];
                const float* s3 = S[4 * kp4 + 3];
                ph1[0] = packh(s2[0], s2[1]); ph1[1] = packh(s2[2], s2[3]);
                ph1[2] = packh(s3[0], s3[1]); ph1[3] = packh(s3[2], s3[3]);
            }
#pragma unroll
            for (int jn = 0; jn < 8; jn++) {
                uint32_t vh4[4];
                ldm_x4_trans(vh4, vh_u + (kp4 * 32 + lane) * 144 + jn * 16);
                mma_f16(o[jn], ph0, vh4[0], vh4[1]);
                mma_f16(o[jn], ph1, vh4[2], vh4[3]);
            }
        }

        // ---- prefetch KV(kt+2) ----
        __syncthreads();
        if (kt + 2 < 16) load_kv(kt + 2, kt & 1);
        CP_COMMIT();
        if (kt + 1 < 16) {
            CP_WAIT1();
            __syncthreads();
        }
    }

    // ---- epilogue: normalize, pack fp16, store (b, s, h*64+d) ----
    float inv0 = 1.0f / l0, inv1 = 1.0f / l1;
    const size_t row0 = (tok0 + qt * 128 + wid * 16 + gr) * 1024 + h * 64;
    const size_t row1 = row0 + 8 * 1024;
#pragma unroll
    for (int jn = 0; jn < 8; jn++) {
        int cc = jn * 8 + 2 * qq;
        *(uint32_t*)&attn[row0 + cc] = packh(o[jn][0] * inv0, o[jn][1] * inv0);
        *(uint32_t*)&attn[row1 + cc] = packh(o[jn][2] * inv1, o[jn][3] * inv1);
    }
}

// ---------------------------------------------------------------------------
// Launch: convert -> QKV GEMM (fp16 out) -> flash (fp16 out) -> out GEMM (fp32)
// ---------------------------------------------------------------------------
extern "C" void kernel_launch(void* const* d_in, const int* in_sizes, int n_in,
                              void* d_out, int out_size) {
    const float* x     = (const float*)d_in[0];  // [2,2048,1024]
    const float* w_qkv = (const float*)d_in[1];  // [3072,1024]
    const float* w_out = (const float*)d_in[2];  // [1024,1024]
    float* out = (float*)d_out;                  // [2,2048,1024]

    __half *xh, *wq, *wo, *qh, *ah;
    cudaGetSymbolAddress((void**)&xh, g_x);
    cudaGetSymbolAddress((void**)&wq, g_wq);
    cudaGetSymbolAddress((void**)&wo, g_wo);
    cudaGetSymbolAddress((void**)&qh, g_q);
    cudaGetSymbolAddress((void**)&ah, g_a);

    cudaFuncSetAttribute(flash_attn, cudaFuncAttributeMaxDynamicSharedMemorySize, FLASH_SMEM);
    cudaFuncSetAttribute(gemm_mma<true>, cudaFuncAttributeMaxDynamicSharedMemorySize, GEMM_SMEM);
    cudaFuncSetAttribute(gemm_mma<false>, cudaFuncAttributeMaxDynamicSharedMemorySize, GEMM_SMEM);

    dim3 blk(256);
    conv_all<<<(X4 + W4 + O4) / 256, blk>>>(x, w_qkv, w_out, xh, wq, wo);
    // QKV: [4096,3072] = x @ wq^T  -> fp16
    gemm_mma<true><<<dim3(3072 / 128, 4096 / 128), blk, GEMM_SMEM>>>(
        xh, wq, nullptr, qh, 1024, 3072);
    // Attention -> fp16
    flash_attn<<<dim3(16, 32), blk, FLASH_SMEM>>>(qh, ah);
    // Out: [4096,1024] = attn @ wo^T -> fp32
    gemm_mma<false><<<dim3(1024 / 128, 4096 / 128), blk, GEMM_SMEM>>>(
        ah, wo, out, nullptr, 1024, 1024);
}